// round 7
// baseline (speedup 1.0000x reference)
#include <cuda_runtime.h>
#include <cuda_bf16.h>
#include <math.h>
#include <float.h>
#include <stdint.h>

// Problem constants
#define BATCH 2
#define SEQ   2048
#define DMODEL 2048
#define NH    32
#define NKV   8
#define REP   4
#define HD    64
#define TOKENS (BATCH*SEQ)   // 4096
#define QDIM  (NH*HD)        // 2048
#define KVDIM (NKV*HD)       // 512

// fp32 scratch
__device__ float g_Q[TOKENS*QDIM];
__device__ float g_K[TOKENS*KVDIM];
__device__ float g_V[TOKENS*KVDIM];
__device__ float g_A[TOKENS*QDIM];
__device__ float g_cos[SEQ*(HD/2)];
__device__ float g_sin[SEQ*(HD/2)];

// bf16 hi/lo decompositions
__device__ __nv_bfloat16 g_xh[TOKENS*DMODEL],  g_xl[TOKENS*DMODEL];
__device__ __nv_bfloat16 g_wqh[DMODEL*QDIM],   g_wql[DMODEL*QDIM];
__device__ __nv_bfloat16 g_wkh[DMODEL*KVDIM],  g_wkl[DMODEL*KVDIM];
__device__ __nv_bfloat16 g_wvh[DMODEL*KVDIM],  g_wvl[DMODEL*KVDIM];
__device__ __nv_bfloat16 g_woh[QDIM*DMODEL],   g_wol[QDIM*DMODEL];
__device__ __nv_bfloat16 g_Ah2[TOKENS*QDIM],   g_Al2[TOKENS*QDIM];

__device__ __forceinline__ uint32_t f2tf32(float x) {
    uint32_t r;
    asm("cvt.rna.tf32.f32 %0, %1;" : "=r"(r) : "f"(x));
    return r;
}
__device__ __forceinline__ float tf32f(float x) {
    return __uint_as_float(f2tf32(x));
}
__device__ __forceinline__ void mma_tf32(float* c, const uint32_t* a, uint32_t b0, uint32_t b1) {
    asm volatile("mma.sync.aligned.m16n8k8.row.col.f32.tf32.tf32.f32 "
                 "{%0,%1,%2,%3}, {%4,%5,%6,%7}, {%8,%9}, {%0,%1,%2,%3};"
                 : "+f"(c[0]), "+f"(c[1]), "+f"(c[2]), "+f"(c[3])
                 : "r"(a[0]), "r"(a[1]), "r"(a[2]), "r"(a[3]), "r"(b0), "r"(b1));
}
__device__ __forceinline__ void mma_bf16(float* c, const uint32_t* a, uint32_t b0, uint32_t b1) {
    asm volatile("mma.sync.aligned.m16n8k16.row.col.f32.bf16.bf16.f32 "
                 "{%0,%1,%2,%3}, {%4,%5,%6,%7}, {%8,%9}, {%0,%1,%2,%3};"
                 : "+f"(c[0]), "+f"(c[1]), "+f"(c[2]), "+f"(c[3])
                 : "r"(a[0]), "r"(a[1]), "r"(a[2]), "r"(a[3]), "r"(b0), "r"(b1));
}
__device__ __forceinline__ void ldmx4(uint32_t* r, uint32_t addr) {
    asm volatile("ldmatrix.sync.aligned.m8n8.x4.shared.b16 {%0,%1,%2,%3}, [%4];"
                 : "=r"(r[0]), "=r"(r[1]), "=r"(r[2]), "=r"(r[3]) : "r"(addr));
}
__device__ __forceinline__ void ldmx4t(uint32_t* r, uint32_t addr) {
    asm volatile("ldmatrix.sync.aligned.m8n8.x4.trans.shared.b16 {%0,%1,%2,%3}, [%4];"
                 : "=r"(r[0]), "=r"(r[1]), "=r"(r[2]), "=r"(r[3]) : "r"(addr));
}
__device__ __forceinline__ void cp_async16(void* smem_dst, const void* gmem_src) {
    uint32_t s = (uint32_t)__cvta_generic_to_shared(smem_dst);
    asm volatile("cp.async.cg.shared.global [%0], [%1], 16;" :: "r"(s), "l"(gmem_src));
}
__device__ __forceinline__ void cp_commit() {
    asm volatile("cp.async.commit_group;");
}
template<int N> __device__ __forceinline__ void cp_wait() {
    asm volatile("cp.async.wait_group %0;" :: "n"(N));
}

// ---------------------------------------------------------------------------
// hi/lo bf16 split (4 elems/thread)
// ---------------------------------------------------------------------------
__global__ void conv_kernel(const float* __restrict__ in,
                            __nv_bfloat16* __restrict__ hi,
                            __nv_bfloat16* __restrict__ lo, int n4) {
    int i = blockIdx.x * blockDim.x + threadIdx.x;
    if (i >= n4) return;
    float4 v = *(const float4*)(in + i*4);
    __nv_bfloat16 h0 = __float2bfloat16(v.x);
    __nv_bfloat16 h1 = __float2bfloat16(v.y);
    __nv_bfloat16 h2 = __float2bfloat16(v.z);
    __nv_bfloat16 h3 = __float2bfloat16(v.w);
    __nv_bfloat16 l0 = __float2bfloat16(v.x - __bfloat162float(h0));
    __nv_bfloat16 l1 = __float2bfloat16(v.y - __bfloat162float(h1));
    __nv_bfloat16 l2 = __float2bfloat16(v.z - __bfloat162float(h2));
    __nv_bfloat16 l3 = __float2bfloat16(v.w - __bfloat162float(h3));
    __nv_bfloat162 hh0; hh0.x = h0; hh0.y = h1;
    __nv_bfloat162 hh1; hh1.x = h2; hh1.y = h3;
    __nv_bfloat162 ll0; ll0.x = l0; ll0.y = l1;
    __nv_bfloat162 ll1; ll1.x = l2; ll1.y = l3;
    *(__nv_bfloat162*)(hi + i*4)     = hh0;
    *(__nv_bfloat162*)(hi + i*4 + 2) = hh1;
    *(__nv_bfloat162*)(lo + i*4)     = ll0;
    *(__nv_bfloat162*)(lo + i*4 + 2) = ll1;
}

// ---------------------------------------------------------------------------
// RoPE tables
// ---------------------------------------------------------------------------
__global__ void rope_table_kernel() {
    int idx = blockIdx.x * blockDim.x + threadIdx.x;
    if (idx >= SEQ*(HD/2)) return;
    int pos = idx >> 5;
    int i   = idx & 31;
    double expo = (2.0 * i) / 64.0;
    float invf = (float)(1.0 / pow(10000.0, expo));
    float fr = (float)pos * invf;
    double a = (double)fr;
    g_cos[idx] = (float)cos(a);
    g_sin[idx] = (float)sin(a);
}

// ---------------------------------------------------------------------------
// bf16x3 pipelined GEMM body. C[M,N] = A[M,2048]*B[2048,N] (fp32 semantics via
// 3-term bf16 split). Block tile 128x128, BK=16, 3-stage cp.async, 256 thr,
// 8 warps 4(M)x2(N), warp tile 32x64. ldmatrix fragment loads.
// Smem per stage (bf16): Ah[128][24], Al[128][24], Bh[16][136], Bl[16][136].
// ---------------------------------------------------------------------------
#define GK 2048
#define NSTG 3
#define APITCH 24
#define BPITCH 136
#define STG_ELEMS (2*128*APITCH + 2*16*BPITCH)   // 10496 bf16
#define AH_OFF 0
#define AL_OFF (128*APITCH)
#define BH_OFF (2*128*APITCH)
#define BL_OFF (2*128*APITCH + 16*BPITCH)
#define GEMM_SMEM (NSTG*STG_ELEMS*2)             // 62976 B

__device__ __forceinline__ void gemm_body(const __nv_bfloat16* __restrict__ Ah,
                                          const __nv_bfloat16* __restrict__ Al,
                                          const __nv_bfloat16* __restrict__ Bh,
                                          const __nv_bfloat16* __restrict__ Bl,
                                          float* __restrict__ C,
                                          int N, int by, int cb, int rope) {
    extern __shared__ __nv_bfloat16 smb[];

    int tid  = threadIdx.x;
    int lane = tid & 31, warp = tid >> 5;
    int wm = warp & 3, wn = warp >> 2;
    int m_warp = wm * 32, n_warp = wn * 64;
    int g  = lane >> 2;
    int tg = lane & 3;

    const __nv_bfloat16* Ahb = Ah + (size_t)by * 128 * GK;
    const __nv_bfloat16* Alb = Al + (size_t)by * 128 * GK;
    const __nv_bfloat16* Bhb = Bh + (size_t)cb * 128;
    const __nv_bfloat16* Blb = Bl + (size_t)cb * 128;

    // cp.async assignments: A row/chunk, B krow/nchunk (1 chunk of 8 bf16 each)
    int a_r = tid >> 1, a_k = (tid & 1) * 8;
    int b_r = tid >> 4, b_n = (tid & 15) * 8;

    float acc[2][8][4];
    #pragma unroll
    for (int mi = 0; mi < 2; mi++)
        #pragma unroll
        for (int ni = 0; ni < 8; ni++)
            #pragma unroll
            for (int c = 0; c < 4; c++) acc[mi][ni][c] = 0.f;

    #pragma unroll
    for (int s = 0; s < NSTG-1; s++) {
        int k0 = s * 16;
        __nv_bfloat16* st = smb + s*STG_ELEMS;
        cp_async16(&st[AH_OFF + a_r*APITCH + a_k], &Ahb[(size_t)a_r*GK + k0 + a_k]);
        cp_async16(&st[AL_OFF + a_r*APITCH + a_k], &Alb[(size_t)a_r*GK + k0 + a_k]);
        cp_async16(&st[BH_OFF + b_r*BPITCH + b_n], &Bhb[(size_t)(k0+b_r)*N + b_n]);
        cp_async16(&st[BL_OFF + b_r*BPITCH + b_n], &Blb[(size_t)(k0+b_r)*N + b_n]);
        cp_commit();
    }

    // ldmatrix lane addressing offsets (in bf16 elems)
    int a_lrow = lane & 15, a_lcol = (lane >> 4) * 8;
    int b_lrow = lane & 15, b_lcol = (lane >> 4) * 8;

    const int NITER = GK / 16;
    int s = 0;
    for (int it = 0; it < NITER; it++) {
        cp_wait<NSTG-2>();
        __syncthreads();

        int kpre = (it + NSTG - 1) * 16;
        if (kpre < GK) {
            int sp = (it + NSTG - 1) % NSTG;
            __nv_bfloat16* st = smb + sp*STG_ELEMS;
            cp_async16(&st[AH_OFF + a_r*APITCH + a_k], &Ahb[(size_t)a_r*GK + kpre + a_k]);
            cp_async16(&st[AL_OFF + a_r*APITCH + a_k], &Alb[(size_t)a_r*GK + kpre + a_k]);
            cp_async16(&st[BH_OFF + b_r*BPITCH + b_n], &Bhb[(size_t)(kpre+b_r)*N + b_n]);
            cp_async16(&st[BL_OFF + b_r*BPITCH + b_n], &Blb[(size_t)(kpre+b_r)*N + b_n]);
        }
        cp_commit();

        __nv_bfloat16* st = smb + s*STG_ELEMS;
        uint32_t ahf[2][4], alf[2][4];
        {
            uint32_t base_h = (uint32_t)__cvta_generic_to_shared(
                &st[AH_OFF + (m_warp + a_lrow)*APITCH + a_lcol]);
            uint32_t base_l = (uint32_t)__cvta_generic_to_shared(
                &st[AL_OFF + (m_warp + a_lrow)*APITCH + a_lcol]);
            ldmx4(ahf[0], base_h);
            ldmx4(ahf[1], base_h + 16*APITCH*2);
            ldmx4(alf[0], base_l);
            ldmx4(alf[1], base_l + 16*APITCH*2);
        }
        #pragma unroll
        for (int nb = 0; nb < 4; nb++) {
            uint32_t bhf[4], blf[4];
            uint32_t base_h = (uint32_t)__cvta_generic_to_shared(
                &st[BH_OFF + b_lrow*BPITCH + n_warp + nb*16 + b_lcol]);
            uint32_t base_l = (uint32_t)__cvta_generic_to_shared(
                &st[BL_OFF + b_lrow*BPITCH + n_warp + nb*16 + b_lcol]);
            ldmx4t(bhf, base_h);
            ldmx4t(blf, base_l);
            #pragma unroll
            for (int mi = 0; mi < 2; mi++) {
                mma_bf16(acc[mi][nb*2],   ahf[mi], bhf[0], bhf[1]);
                mma_bf16(acc[mi][nb*2],   ahf[mi], blf[0], blf[1]);
                mma_bf16(acc[mi][nb*2],   alf[mi], bhf[0], bhf[1]);
                mma_bf16(acc[mi][nb*2+1], ahf[mi], bhf[2], bhf[3]);
                mma_bf16(acc[mi][nb*2+1], ahf[mi], blf[2], blf[3]);
                mma_bf16(acc[mi][nb*2+1], alf[mi], bhf[2], bhf[3]);
            }
        }
        s = (s + 1) % NSTG;
    }

    // ---- optional fused RoPE epilogue (warp tile spans exactly one head) ----
    if (rope) {
        #pragma unroll
        for (int mi = 0; mi < 2; mi++) {
            int ra = by*128 + m_warp + mi*16 + g;
            int pa = ra & (SEQ-1);
            int pb = (ra + 8) & (SEQ-1);
            #pragma unroll
            for (int ni = 0; ni < 4; ni++) {
                int i0 = ni*8 + tg*2;
                float ca0 = g_cos[pa*32 + i0],   sa0 = g_sin[pa*32 + i0];
                float ca1 = g_cos[pa*32 + i0+1], sa1 = g_sin[pa*32 + i0+1];
                float cb0 = g_cos[pb*32 + i0],   sb0 = g_sin[pb*32 + i0];
                float cb1 = g_cos[pb*32 + i0+1], sb1 = g_sin[pb*32 + i0+1];
                float x1, x2;
                x1 = acc[mi][ni][0]; x2 = acc[mi][ni+4][0];
                acc[mi][ni][0] = x1*ca0 - x2*sa0; acc[mi][ni+4][0] = x1*sa0 + x2*ca0;
                x1 = acc[mi][ni][1]; x2 = acc[mi][ni+4][1];
                acc[mi][ni][1] = x1*ca1 - x2*sa1; acc[mi][ni+4][1] = x1*sa1 + x2*ca1;
                x1 = acc[mi][ni][2]; x2 = acc[mi][ni+4][2];
                acc[mi][ni][2] = x1*cb0 - x2*sb0; acc[mi][ni+4][2] = x1*sb0 + x2*cb0;
                x1 = acc[mi][ni][3]; x2 = acc[mi][ni+4][3];
                acc[mi][ni][3] = x1*cb1 - x2*sb1; acc[mi][ni+4][3] = x1*sb1 + x2*cb1;
            }
        }
    }

    size_t rowbase = (size_t)by * 128 + m_warp + g;
    int colbase = cb * 128 + n_warp + tg*2;
    #pragma unroll
    for (int mi = 0; mi < 2; mi++) {
        size_t r0 = rowbase + mi*16;
        #pragma unroll
        for (int ni = 0; ni < 8; ni++) {
            int c = colbase + ni*8;
            *(float2*)&C[r0*N + c]     = make_float2(acc[mi][ni][0], acc[mi][ni][1]);
            *(float2*)&C[(r0+8)*N + c] = make_float2(acc[mi][ni][2], acc[mi][ni][3]);
        }
    }
}

// Fused QKV projection + RoPE. grid=(24,32): bx 0..15 Q, 16..19 K, 20..23 V
__global__ __launch_bounds__(256) void qkv_kernel() {
    int bx = blockIdx.x;
    const __nv_bfloat16 *B, *Bl; float* C; int N, cb, rope;
    if (bx < 16)      { B = g_wqh; Bl = g_wql; C = g_Q; N = QDIM;  cb = bx;      rope = 1; }
    else if (bx < 20) { B = g_wkh; Bl = g_wkl; C = g_K; N = KVDIM; cb = bx - 16; rope = 1; }
    else              { B = g_wvh; Bl = g_wvl; C = g_V; N = KVDIM; cb = bx - 20; rope = 0; }
    gemm_body(g_xh, g_xl, B, Bl, C, N, blockIdx.y, cb, rope);
}

// Output projection. grid=(16,32)
__global__ __launch_bounds__(256) void outproj_kernel(float* __restrict__ out) {
    gemm_body(g_Ah2, g_Al2, g_woh, g_wol, out, DMODEL, blockIdx.y, blockIdx.x, 0);
}

// ---------------------------------------------------------------------------
// Tensor-core causal flash attention, 3xTF32 (unchanged from R6).
// ---------------------------------------------------------------------------
#define FPAD 68
#define VPAD 72
#define FLASH_SMEM ((3*64*FPAD + 2*64*VPAD)*4)   // 89088 bytes

__global__ __launch_bounds__(128) void flash_tc(const float* __restrict__ Q,
                                                const float* __restrict__ K,
                                                const float* __restrict__ V,
                                                float* __restrict__ O) {
    extern __shared__ float sm[];
    float* Qs = sm;
    float* Kh = Qs + 64*FPAD;
    float* Kl = Kh + 64*FPAD;
    float* Vh = Kl + 64*FPAD;
    float* Vl = Vh + 64*VPAD;
    float* Ps = Kh;

    int qt = blockIdx.x;
    int bh = blockIdx.y;
    int b = bh >> 5, h = bh & 31, gkv = h >> 2;
    int tid = threadIdx.x;
    int lane = tid & 31, warp = tid >> 5;
    int g = lane >> 2, tg = lane & 3;
    int m0 = warp * 16;

    const float* Qbase = Q + (size_t)b*SEQ*QDIM + (size_t)(qt*64)*QDIM + h*64;
    const float* Kbase = K + (size_t)b*SEQ*KVDIM + gkv*64;
    const float* Vbase = V + (size_t)b*SEQ*KVDIM + gkv*64;

    {
        int r = tid >> 1, c0 = (tid & 1) * 32;
        const float* src = Qbase + (size_t)r*QDIM + c0;
        float* dst = Qs + r*FPAD + c0;
        #pragma unroll
        for (int i = 0; i < 8; i++)
            *(float4*)(dst + i*4) = *(const float4*)(src + i*4);
    }

    float m_i[2] = {-FLT_MAX, -FLT_MAX};
    float l_i[2] = {0.f, 0.f};
    float o[8][4];
    #pragma unroll
    for (int nf = 0; nf < 8; nf++)
        #pragma unroll
        for (int c = 0; c < 4; c++) o[nf][c] = 0.f;

    const float scale = 0.125f;

    for (int kt = 0; kt <= qt; kt++) {
        __syncthreads();
        {
            int r = tid >> 1, c0 = (tid & 1) * 32;
            const float* ksrc = Kbase + (size_t)(kt*64 + r)*KVDIM + c0;
            const float* vsrc = Vbase + (size_t)(kt*64 + r)*KVDIM + c0;
            float* khd = Kh + r*FPAD + c0;
            float* kld = Kl + r*FPAD + c0;
            float* vhd = Vh + r*VPAD + c0;
            float* vld = Vl + r*VPAD + c0;
            #pragma unroll
            for (int i = 0; i < 8; i++) {
                float4 kv = *(const float4*)(ksrc + i*4);
                float4 vv = *(const float4*)(vsrc + i*4);
                float4 kh4, kl4, vh4, vl4;
                kh4.x = tf32f(kv.x); kl4.x = tf32f(kv.x - kh4.x);
                kh4.y = tf32f(kv.y); kl4.y = tf32f(kv.y - kh4.y);
                kh4.z = tf32f(kv.z); kl4.z = tf32f(kv.z - kh4.z);
                kh4.w = tf32f(kv.w); kl4.w = tf32f(kv.w - kh4.w);
                vh4.x = tf32f(vv.x); vl4.x = tf32f(vv.x - vh4.x);
                vh4.y = tf32f(vv.y); vl4.y = tf32f(vv.y - vh4.y);
                vh4.z = tf32f(vv.z); vl4.z = tf32f(vv.z - vh4.z);
                vh4.w = tf32f(vv.w); vl4.w = tf32f(vv.w - vh4.w);
                *(float4*)(khd + i*4) = kh4;
                *(float4*)(kld + i*4) = kl4;
                *(float4*)(vhd + i*4) = vh4;
                *(float4*)(vld + i*4) = vl4;
            }
        }
        __syncthreads();

        float s[8][4];
        #pragma unroll
        for (int nf = 0; nf < 8; nf++)
            #pragma unroll
            for (int c = 0; c < 4; c++) s[nf][c] = 0.f;

        #pragma unroll 2
        for (int kk = 0; kk < 64; kk += 8) {
            float a0 = Qs[(m0+g)*FPAD   + kk+tg];
            float a1 = Qs[(m0+g+8)*FPAD + kk+tg];
            float a2 = Qs[(m0+g)*FPAD   + kk+tg+4];
            float a3 = Qs[(m0+g+8)*FPAD + kk+tg+4];
            uint32_t ah[4], al[4];
            ah[0] = f2tf32(a0); al[0] = f2tf32(a0 - __uint_as_float(ah[0]));
            ah[1] = f2tf32(a1); al[1] = f2tf32(a1 - __uint_as_float(ah[1]));
            ah[2] = f2tf32(a2); al[2] = f2tf32(a2 - __uint_as_float(ah[2]));
            ah[3] = f2tf32(a3); al[3] = f2tf32(a3 - __uint_as_float(ah[3]));
            #pragma unroll
            for (int nf = 0; nf < 8; nf++) {
                uint32_t bh0 = __float_as_uint(Kh[(nf*8+g)*FPAD + kk+tg]);
                uint32_t bh1 = __float_as_uint(Kh[(nf*8+g)*FPAD + kk+tg+4]);
                uint32_t bl0 = __float_as_uint(Kl[(nf*8+g)*FPAD + kk+tg]);
                uint32_t bl1 = __float_as_uint(Kl[(nf*8+g)*FPAD + kk+tg+4]);
                mma_tf32(s[nf], ah, bh0, bh1);
                mma_tf32(s[nf], ah, bl0, bl1);
                mma_tf32(s[nf], al, bh0, bh1);
            }
        }

        if (kt == qt) {
            int r0l = m0 + g, r1l = r0l + 8;
            #pragma unroll
            for (int nf = 0; nf < 8; nf++) {
                int c0 = nf*8 + 2*tg, c1 = c0 + 1;
                s[nf][0] = (c0 > r0l) ? -FLT_MAX : s[nf][0]*scale;
                s[nf][1] = (c1 > r0l) ? -FLT_MAX : s[nf][1]*scale;
                s[nf][2] = (c0 > r1l) ? -FLT_MAX : s[nf][2]*scale;
                s[nf][3] = (c1 > r1l) ? -FLT_MAX : s[nf][3]*scale;
            }
        } else {
            #pragma unroll
            for (int nf = 0; nf < 8; nf++)
                #pragma unroll
                for (int c = 0; c < 4; c++) s[nf][c] *= scale;
        }

        float rm0 = -FLT_MAX, rm1 = -FLT_MAX;
        #pragma unroll
        for (int nf = 0; nf < 8; nf++) {
            rm0 = fmaxf(rm0, fmaxf(s[nf][0], s[nf][1]));
            rm1 = fmaxf(rm1, fmaxf(s[nf][2], s[nf][3]));
        }
        rm0 = fmaxf(rm0, __shfl_xor_sync(0xffffffffu, rm0, 1));
        rm0 = fmaxf(rm0, __shfl_xor_sync(0xffffffffu, rm0, 2));
        rm1 = fmaxf(rm1, __shfl_xor_sync(0xffffffffu, rm1, 1));
        rm1 = fmaxf(rm1, __shfl_xor_sync(0xffffffffu, rm1, 2));
        float mn0 = fmaxf(m_i[0], rm0), mn1 = fmaxf(m_i[1], rm1);
        float fac0 = __expf(m_i[0] - mn0), fac1 = __expf(m_i[1] - mn1);
        m_i[0] = mn0; m_i[1] = mn1;
        float rs0 = 0.f, rs1 = 0.f;
        #pragma unroll
        for (int nf = 0; nf < 8; nf++) {
            s[nf][0] = __expf(s[nf][0] - mn0); rs0 += s[nf][0];
            s[nf][1] = __expf(s[nf][1] - mn0); rs0 += s[nf][1];
            s[nf][2] = __expf(s[nf][2] - mn1); rs1 += s[nf][2];
            s[nf][3] = __expf(s[nf][3] - mn1); rs1 += s[nf][3];
        }
        rs0 += __shfl_xor_sync(0xffffffffu, rs0, 1);
        rs0 += __shfl_xor_sync(0xffffffffu, rs0, 2);
        rs1 += __shfl_xor_sync(0xffffffffu, rs1, 1);
        rs1 += __shfl_xor_sync(0xffffffffu, rs1, 2);
        l_i[0] = l_i[0]*fac0 + rs0;
        l_i[1] = l_i[1]*fac1 + rs1;
        #pragma unroll
        for (int nf = 0; nf < 8; nf++) {
            o[nf][0] *= fac0; o[nf][1] *= fac0;
            o[nf][2] *= fac1; o[nf][3] *= fac1;
        }

        __syncthreads();
        #pragma unroll
        for (int nf = 0; nf < 8; nf++) {
            *(float2*)&Ps[(m0+g)*FPAD   + nf*8 + 2*tg] = make_float2(s[nf][0], s[nf][1]);
            *(float2*)&Ps[(m0+g+8)*FPAD + nf*8 + 2*tg] = make_float2(s[nf][2], s[nf][3]);
        }
        __syncwarp();

        #pragma unroll 2
        for (int kk = 0; kk < 64; kk += 8) {
            float a0 = Ps[(m0+g)*FPAD   + kk+tg];
            float a1 = Ps[(m0+g+8)*FPAD + kk+tg];
            float a2 = Ps[(m0+g)*FPAD   + kk+tg+4];
            float a3 = Ps[(m0+g+8)*FPAD + kk+tg+4];
            uint32_t ah[4], al[4];
            ah[0] = f2tf32(a0); al[0] = f2tf32(a0 - __uint_as_float(ah[0]));
            ah[1] = f2tf32(a1); al[1] = f2tf32(a1 - __uint_as_float(ah[1]));
            ah[2] = f2tf32(a2); al[2] = f2tf32(a2 - __uint_as_float(ah[2]));
            ah[3] = f2tf32(a3); al[3] = f2tf32(a3 - __uint_as_float(ah[3]));
            #pragma unroll
            for (int nf = 0; nf < 8; nf++) {
                uint32_t bh0 = __float_as_uint(Vh[(kk+tg)*VPAD   + nf*8+g]);
                uint32_t bh1 = __float_as_uint(Vh[(kk+tg+4)*VPAD + nf*8+g]);
                uint32_t bl0 = __float_as_uint(Vl[(kk+tg)*VPAD   + nf*8+g]);
                uint32_t bl1 = __float_as_uint(Vl[(kk+tg+4)*VPAD + nf*8+g]);
                mma_tf32(o[nf], ah, bh0, bh1);
                mma_tf32(o[nf], ah, bl0, bl1);
                mma_tf32(o[nf], al, bh0, bh1);
            }
        }
    }

    float inv0 = 1.0f / l_i[0], inv1 = 1.0f / l_i[1];
    size_t r0 = (size_t)b*SEQ + qt*64 + m0 + g;
    float* dst0 = O + r0*QDIM + h*64;
    float* dst1 = dst0 + (size_t)8*QDIM;
    #pragma unroll
    for (int nf = 0; nf < 8; nf++) {
        *(float2*)&dst0[nf*8 + 2*tg] = make_float2(o[nf][0]*inv0, o[nf][1]*inv0);
        *(float2*)&dst1[nf*8 + 2*tg] = make_float2(o[nf][2]*inv1, o[nf][3]*inv1);
    }
}

// ---------------------------------------------------------------------------
extern "C" void kernel_launch(void* const* d_in, const int* in_sizes, int n_in,
                              void* d_out, int out_size) {
    (void)in_sizes; (void)n_in; (void)out_size;
    const float* x  = (const float*)d_in[0];
    const float* wq = (const float*)d_in[1];
    const float* wk = (const float*)d_in[2];
    const float* wv = (const float*)d_in[3];
    const float* wo = (const float*)d_in[4];
    float* out = (float*)d_out;

    float *Qp, *Kp, *Vp, *Ap;
    cudaGetSymbolAddress((void**)&Qp, g_Q);
    cudaGetSymbolAddress((void**)&Kp, g_K);
    cudaGetSymbolAddress((void**)&Vp, g_V);
    cudaGetSymbolAddress((void**)&Ap, g_A);

    __nv_bfloat16 *xh, *xl, *wqh, *wql, *wkh, *wkl, *wvh, *wvl, *woh, *wol, *Ah2, *Al2;
    cudaGetSymbolAddress((void**)&xh,  g_xh);  cudaGetSymbolAddress((void**)&xl,  g_xl);
    cudaGetSymbolAddress((void**)&wqh, g_wqh); cudaGetSymbolAddress((void**)&wql, g_wql);
    cudaGetSymbolAddress((void**)&wkh, g_wkh); cudaGetSymbolAddress((void**)&wkl, g_wkl);
    cudaGetSymbolAddress((void**)&wvh, g_wvh); cudaGetSymbolAddress((void**)&wvl, g_wvl);
    cudaGetSymbolAddress((void**)&woh, g_woh); cudaGetSymbolAddress((void**)&wol, g_wol);
    cudaGetSymbolAddress((void**)&Ah2, g_Ah2); cudaGetSymbolAddress((void**)&Al2, g_Al2);

    static int attr_set = 0;
    if (!attr_set) {
        cudaFuncSetAttribute(flash_tc, cudaFuncAttributeMaxDynamicSharedMemorySize, FLASH_SMEM);
        cudaFuncSetAttribute(qkv_kernel, cudaFuncAttributeMaxDynamicSharedMemorySize, GEMM_SMEM);
        cudaFuncSetAttribute(outproj_kernel, cudaFuncAttributeMaxDynamicSharedMemorySize, GEMM_SMEM);
        attr_set = 1;
    }

    rope_table_kernel<<<(SEQ*32 + 255)/256, 256>>>();

    conv_kernel<<<(TOKENS*DMODEL/4 + 255)/256, 256>>>(x,  xh,  xl,  TOKENS*DMODEL/4);
    conv_kernel<<<(DMODEL*QDIM/4  + 255)/256, 256>>>(wq, wqh, wql, DMODEL*QDIM/4);
    conv_kernel<<<(DMODEL*KVDIM/4 + 255)/256, 256>>>(wk, wkh, wkl, DMODEL*KVDIM/4);
    conv_kernel<<<(DMODEL*KVDIM/4 + 255)/256, 256>>>(wv, wvh, wvl, DMODEL*KVDIM/4);
    conv_kernel<<<(QDIM*DMODEL/4  + 255)/256, 256>>>(wo, woh, wol, QDIM*DMODEL/4);

    qkv_kernel<<<dim3(24, TOKENS/128), 256, GEMM_SMEM>>>();

    flash_tc<<<dim3(SEQ/64, BATCH*NH), 128, FLASH_SMEM>>>(Qp, Kp, Vp, Ap);

    conv_kernel<<<(TOKENS*QDIM/4 + 255)/256, 256>>>(Ap, Ah2, Al2, TOKENS*QDIM/4);

    outproj_kernel<<<dim3(DMODEL/128, TOKENS/128), 256, GEMM_SMEM>>>(out);
}

// round 8
// speedup vs baseline: 1.1861x; 1.1861x over previous
#include <cuda_runtime.h>
#include <cuda_bf16.h>
#include <math.h>
#include <float.h>
#include <stdint.h>

// Problem constants
#define BATCH 2
#define SEQ   2048
#define DMODEL 2048
#define NH    32
#define NKV   8
#define REP   4
#define HD    64
#define TOKENS (BATCH*SEQ)   // 4096
#define QDIM  (NH*HD)        // 2048
#define KVDIM (NKV*HD)       // 512

// Scratch (device globals: allocation-free)
__device__ float g_Qh[TOKENS*QDIM],  g_Ql[TOKENS*QDIM];    // pre-scaled tf32 split Q
__device__ float g_Kh[TOKENS*KVDIM], g_Kl[TOKENS*KVDIM];
__device__ float g_Vh[TOKENS*KVDIM], g_Vl[TOKENS*KVDIM];
__device__ float g_A[TOKENS*QDIM];
__device__ float g_cos[SEQ*(HD/2)];
__device__ float g_sin[SEQ*(HD/2)];

__device__ __forceinline__ uint32_t f2tf32(float x) {
    uint32_t r;
    asm("cvt.rna.tf32.f32 %0, %1;" : "=r"(r) : "f"(x));
    return r;
}
__device__ __forceinline__ float tf32f(float x) {
    return __uint_as_float(f2tf32(x));
}
__device__ __forceinline__ void mma_tf32(float* c, const uint32_t* a, uint32_t b0, uint32_t b1) {
    asm volatile("mma.sync.aligned.m16n8k8.row.col.f32.tf32.tf32.f32 "
                 "{%0,%1,%2,%3}, {%4,%5,%6,%7}, {%8,%9}, {%0,%1,%2,%3};"
                 : "+f"(c[0]), "+f"(c[1]), "+f"(c[2]), "+f"(c[3])
                 : "r"(a[0]), "r"(a[1]), "r"(a[2]), "r"(a[3]), "r"(b0), "r"(b1));
}
__device__ __forceinline__ void cp_async16(void* smem_dst, const void* gmem_src) {
    uint32_t s = (uint32_t)__cvta_generic_to_shared(smem_dst);
    asm volatile("cp.async.cg.shared.global [%0], [%1], 16;" :: "r"(s), "l"(gmem_src));
}
__device__ __forceinline__ void cp_commit() {
    asm volatile("cp.async.commit_group;");
}
template<int N> __device__ __forceinline__ void cp_wait() {
    asm volatile("cp.async.wait_group %0;" :: "n"(N));
}

// ---------------------------------------------------------------------------
// RoPE tables
// ---------------------------------------------------------------------------
__global__ void rope_table_kernel() {
    int idx = blockIdx.x * blockDim.x + threadIdx.x;
    if (idx >= SEQ*(HD/2)) return;
    int pos = idx >> 5;
    int i   = idx & 31;
    double expo = (2.0 * i) / 64.0;
    float invf = (float)(1.0 / pow(10000.0, expo));
    float fr = (float)pos * invf;
    double a = (double)fr;
    g_cos[idx] = (float)cos(a);
    g_sin[idx] = (float)sin(a);
}

// ---------------------------------------------------------------------------
// Pipelined tf32 GEMM body (R6) + configurable epilogue:
//   mode bit0: RoPE   bit1: scale 0.125   bit2: split into (Ch, Cl) tf32 hi/lo
// ---------------------------------------------------------------------------
#define GK 2048
#define NSTG 3
#define APITCH 20
#define BPITCH 136
#define ASTG (128*APITCH)
#define BSTG (16*BPITCH)
#define GEMM_SMEM (NSTG*(ASTG+BSTG)*4)   // 56832 B

__device__ __forceinline__ void gemm_body(const float* __restrict__ A,
                                          const float* __restrict__ B,
                                          float* __restrict__ Ch,
                                          float* __restrict__ Cl,
                                          int N, int by, int cb, int mode) {
    extern __shared__ float sm[];
    float* As = sm;
    float* Bs = sm + NSTG*ASTG;

    int tid  = threadIdx.x;
    int lane = tid & 31, warp = tid >> 5;
    int wm = warp & 3, wn = warp >> 2;
    int m_warp = wm * 32, n_warp = wn * 64;
    int g  = lane >> 2;
    int tg = lane & 3;

    const float* Ablk = A + (size_t)by * 128 * GK;
    const float* Bblk = B + (size_t)cb * 128;

    int a_r0 = tid >> 1, a_k0 = (tid & 1) * 8;
    int b_r0 = tid >> 4, b_n0 = (tid & 15) * 8;

    float acc[2][8][4];
    #pragma unroll
    for (int mi = 0; mi < 2; mi++)
        #pragma unroll
        for (int ni = 0; ni < 8; ni++)
            #pragma unroll
            for (int c = 0; c < 4; c++) acc[mi][ni][c] = 0.f;

    #pragma unroll
    for (int s = 0; s < NSTG-1; s++) {
        int k0 = s * 16;
        float* as = As + s*ASTG;
        float* bs = Bs + s*BSTG;
        cp_async16(&as[a_r0*APITCH + a_k0],     &Ablk[(size_t)a_r0*GK + k0 + a_k0]);
        cp_async16(&as[a_r0*APITCH + a_k0 + 4], &Ablk[(size_t)a_r0*GK + k0 + a_k0 + 4]);
        cp_async16(&bs[b_r0*BPITCH + b_n0],     &Bblk[(size_t)(k0+b_r0)*N + b_n0]);
        cp_async16(&bs[b_r0*BPITCH + b_n0 + 4], &Bblk[(size_t)(k0+b_r0)*N + b_n0 + 4]);
        cp_commit();
    }

    const int NITER = GK / 16;
    int s = 0;
    for (int it = 0; it < NITER; it++) {
        cp_wait<NSTG-2>();
        __syncthreads();

        int kpre = (it + NSTG - 1) * 16;
        if (kpre < GK) {
            int sp = (it + NSTG - 1) % NSTG;
            float* as = As + sp*ASTG;
            float* bs = Bs + sp*BSTG;
            cp_async16(&as[a_r0*APITCH + a_k0],     &Ablk[(size_t)a_r0*GK + kpre + a_k0]);
            cp_async16(&as[a_r0*APITCH + a_k0 + 4], &Ablk[(size_t)a_r0*GK + kpre + a_k0 + 4]);
            cp_async16(&bs[b_r0*BPITCH + b_n0],     &Bblk[(size_t)(kpre+b_r0)*N + b_n0]);
            cp_async16(&bs[b_r0*BPITCH + b_n0 + 4], &Bblk[(size_t)(kpre+b_r0)*N + b_n0 + 4]);
        }
        cp_commit();

        const float* as = As + s*ASTG;
        const float* bs = Bs + s*BSTG;
        #pragma unroll
        for (int kk = 0; kk < 16; kk += 8) {
            uint32_t afr[2][4];
            #pragma unroll
            for (int mi = 0; mi < 2; mi++) {
                int mb = m_warp + mi*16;
                afr[mi][0] = f2tf32(as[(mb+g)*APITCH   + kk+tg]);
                afr[mi][1] = f2tf32(as[(mb+g+8)*APITCH + kk+tg]);
                afr[mi][2] = f2tf32(as[(mb+g)*APITCH   + kk+tg+4]);
                afr[mi][3] = f2tf32(as[(mb+g+8)*APITCH + kk+tg+4]);
            }
            uint32_t bfr[8][2];
            #pragma unroll
            for (int ni = 0; ni < 8; ni++) {
                int nb = n_warp + ni*8;
                bfr[ni][0] = f2tf32(bs[(kk+tg)*BPITCH   + nb + g]);
                bfr[ni][1] = f2tf32(bs[(kk+tg+4)*BPITCH + nb + g]);
            }
            #pragma unroll
            for (int mi = 0; mi < 2; mi++)
                #pragma unroll
                for (int ni = 0; ni < 8; ni++)
                    mma_tf32(acc[mi][ni], afr[mi], bfr[ni][0], bfr[ni][1]);
        }
        s = (s + 1) % NSTG;
    }

    // ---- fused RoPE (warp tile spans exactly one head) ----
    if (mode & 1) {
        #pragma unroll
        for (int mi = 0; mi < 2; mi++) {
            int ra = by*128 + m_warp + mi*16 + g;
            int pa = ra & (SEQ-1);
            int pb = (ra + 8) & (SEQ-1);
            #pragma unroll
            for (int ni = 0; ni < 4; ni++) {
                int i0 = ni*8 + tg*2;
                float ca0 = g_cos[pa*32 + i0],   sa0 = g_sin[pa*32 + i0];
                float ca1 = g_cos[pa*32 + i0+1], sa1 = g_sin[pa*32 + i0+1];
                float cb0 = g_cos[pb*32 + i0],   sb0 = g_sin[pb*32 + i0];
                float cb1 = g_cos[pb*32 + i0+1], sb1 = g_sin[pb*32 + i0+1];
                float x1, x2;
                x1 = acc[mi][ni][0]; x2 = acc[mi][ni+4][0];
                acc[mi][ni][0] = x1*ca0 - x2*sa0; acc[mi][ni+4][0] = x1*sa0 + x2*ca0;
                x1 = acc[mi][ni][1]; x2 = acc[mi][ni+4][1];
                acc[mi][ni][1] = x1*ca1 - x2*sa1; acc[mi][ni+4][1] = x1*sa1 + x2*ca1;
                x1 = acc[mi][ni][2]; x2 = acc[mi][ni+4][2];
                acc[mi][ni][2] = x1*cb0 - x2*sb0; acc[mi][ni+4][2] = x1*sb0 + x2*cb0;
                x1 = acc[mi][ni][3]; x2 = acc[mi][ni+4][3];
                acc[mi][ni][3] = x1*cb1 - x2*sb1; acc[mi][ni+4][3] = x1*sb1 + x2*cb1;
            }
        }
    }

    float mul = (mode & 2) ? 0.125f : 1.0f;
    size_t rowbase = (size_t)by * 128 + m_warp + g;
    int colbase = cb * 128 + n_warp + tg*2;
    if (mode & 4) {
        #pragma unroll
        for (int mi = 0; mi < 2; mi++) {
            size_t r0 = rowbase + mi*16;
            #pragma unroll
            for (int ni = 0; ni < 8; ni++) {
                int c = colbase + ni*8;
                float v0 = acc[mi][ni][0]*mul, v1 = acc[mi][ni][1]*mul;
                float v2 = acc[mi][ni][2]*mul, v3 = acc[mi][ni][3]*mul;
                float h0 = tf32f(v0), h1 = tf32f(v1), h2 = tf32f(v2), h3 = tf32f(v3);
                *(float2*)&Ch[r0*N + c]     = make_float2(h0, h1);
                *(float2*)&Ch[(r0+8)*N + c] = make_float2(h2, h3);
                *(float2*)&Cl[r0*N + c]     = make_float2(tf32f(v0-h0), tf32f(v1-h1));
                *(float2*)&Cl[(r0+8)*N + c] = make_float2(tf32f(v2-h2), tf32f(v3-h3));
            }
        }
    } else {
        #pragma unroll
        for (int mi = 0; mi < 2; mi++) {
            size_t r0 = rowbase + mi*16;
            #pragma unroll
            for (int ni = 0; ni < 8; ni++) {
                int c = colbase + ni*8;
                *(float2*)&Ch[r0*N + c]     = make_float2(acc[mi][ni][0], acc[mi][ni][1]);
                *(float2*)&Ch[(r0+8)*N + c] = make_float2(acc[mi][ni][2], acc[mi][ni][3]);
            }
        }
    }
}

// Fused QKV projection + RoPE + tf32-split. grid=(24,32)
__global__ __launch_bounds__(256) void qkv_kernel(const float* __restrict__ x,
                                                  const float* __restrict__ wq,
                                                  const float* __restrict__ wk,
                                                  const float* __restrict__ wv) {
    int bx = blockIdx.x;
    const float* B; float *Ch, *Cl; int N, cb, mode;
    if (bx < 16)      { B = wq; Ch = g_Qh; Cl = g_Ql; N = QDIM;  cb = bx;      mode = 7; } // rope+scale+split
    else if (bx < 20) { B = wk; Ch = g_Kh; Cl = g_Kl; N = KVDIM; cb = bx - 16; mode = 5; } // rope+split
    else              { B = wv; Ch = g_Vh; Cl = g_Vl; N = KVDIM; cb = bx - 20; mode = 4; } // split
    gemm_body(x, B, Ch, Cl, N, blockIdx.y, cb, mode);
}

// Output projection. grid=(16,32)
__global__ __launch_bounds__(256) void outproj_kernel(const float* __restrict__ wo,
                                                      float* __restrict__ out) {
    gemm_body(g_A, wo, out, nullptr, DMODEL, blockIdx.y, blockIdx.x, 0);
}

// ---------------------------------------------------------------------------
// Flash attention v2: 3xTF32, q-tile 128, 256 threads = 8 warps (16 rows each).
// Q/K/V pre-split tf32 hi/lo in gmem (Q pre-scaled); tiles loaded via cp.async.
// P aliases the K region. Per-warp causal tile skip.
// ---------------------------------------------------------------------------
#define F2PAD 68
#define V2PAD 72
#define QH_OFF 0
#define QL_OFF (128*F2PAD)
#define KH_OFF (2*128*F2PAD)
#define KL_OFF (KH_OFF + 64*F2PAD)
#define VH_OFF (KH_OFF + 2*64*F2PAD)
#define VL_OFF (VH_OFF + 64*V2PAD)
#define FL2_SMEM ((2*128*F2PAD + 2*64*F2PAD + 2*64*V2PAD)*4)   // 141312 B

__global__ __launch_bounds__(256) void flash2(float* __restrict__ O) {
    extern __shared__ float sm[];
    float* Ps = sm + KH_OFF;   // [128][F2PAD], aliases Kh+Kl

    int qt = blockIdx.x;                 // 0..15
    int bh = blockIdx.y;
    int b = bh >> 5, h = bh & 31, gkv = h >> 2;
    int tid = threadIdx.x;
    int lane = tid & 31, warp = tid >> 5;
    int g = lane >> 2, tg = lane & 3;
    int m0 = warp * 16;

    const float* Qhb = g_Qh + ((size_t)b*SEQ + qt*128)*QDIM + h*64;
    const float* Qlb = g_Ql + ((size_t)b*SEQ + qt*128)*QDIM + h*64;
    const float* Khb = g_Kh + (size_t)b*SEQ*KVDIM + gkv*64;
    const float* Klb = g_Kl + (size_t)b*SEQ*KVDIM + gkv*64;
    const float* Vhb = g_Vh + (size_t)b*SEQ*KVDIM + gkv*64;
    const float* Vlb = g_Vl + (size_t)b*SEQ*KVDIM + gkv*64;

    // Load Q tile (hi+lo), 128 rows x 64 cols: 2048 16B-chunks per array
    #pragma unroll
    for (int j = 0; j < 8; j++) {
        int ci = tid + j*256;
        int r = ci >> 4, q = ci & 15;
        cp_async16(&sm[QH_OFF + r*F2PAD + q*4], &Qhb[(size_t)r*QDIM + q*4]);
        cp_async16(&sm[QL_OFF + r*F2PAD + q*4], &Qlb[(size_t)r*QDIM + q*4]);
    }
    cp_commit();

    float m_i[2] = {-FLT_MAX, -FLT_MAX};
    float l_i[2] = {0.f, 0.f};
    float o[8][4];
    #pragma unroll
    for (int nf = 0; nf < 8; nf++)
        #pragma unroll
        for (int c = 0; c < 4; c++) o[nf][c] = 0.f;

    int ktmax = (128*qt + 16*warp + 15) >> 6;   // last tile this warp touches
    int kt_end = 2*qt + 1;

    for (int kt = 0; kt <= kt_end; kt++) {
        __syncthreads();   // previous P / V fully consumed
        // Load K,V tiles (hi+lo): 64 rows x 64 cols each
        #pragma unroll
        for (int j = 0; j < 4; j++) {
            int ci = tid + j*256;
            int r = ci >> 4, q = ci & 15;
            size_t go = (size_t)(kt*64 + r)*KVDIM + q*4;
            cp_async16(&sm[KH_OFF + r*F2PAD + q*4], Khb + go);
            cp_async16(&sm[KL_OFF + r*F2PAD + q*4], Klb + go);
            cp_async16(&sm[VH_OFF + r*V2PAD + q*4], Vhb + go);
            cp_async16(&sm[VL_OFF + r*V2PAD + q*4], Vlb + go);
        }
        cp_commit();
        cp_wait<0>();
        __syncthreads();

        bool active = (kt <= ktmax);
        float s[8][4];
        if (active) {
            #pragma unroll
            for (int nf = 0; nf < 8; nf++)
                #pragma unroll
                for (int c = 0; c < 4; c++) s[nf][c] = 0.f;

            #pragma unroll 2
            for (int kk = 0; kk < 64; kk += 8) {
                uint32_t ah[4], al[4];
                ah[0] = __float_as_uint(sm[QH_OFF + (m0+g)*F2PAD   + kk+tg]);
                ah[1] = __float_as_uint(sm[QH_OFF + (m0+g+8)*F2PAD + kk+tg]);
                ah[2] = __float_as_uint(sm[QH_OFF + (m0+g)*F2PAD   + kk+tg+4]);
                ah[3] = __float_as_uint(sm[QH_OFF + (m0+g+8)*F2PAD + kk+tg+4]);
                al[0] = __float_as_uint(sm[QL_OFF + (m0+g)*F2PAD   + kk+tg]);
                al[1] = __float_as_uint(sm[QL_OFF + (m0+g+8)*F2PAD + kk+tg]);
                al[2] = __float_as_uint(sm[QL_OFF + (m0+g)*F2PAD   + kk+tg+4]);
                al[3] = __float_as_uint(sm[QL_OFF + (m0+g+8)*F2PAD + kk+tg+4]);
                #pragma unroll
                for (int nf = 0; nf < 8; nf++) {
                    uint32_t bh0 = __float_as_uint(sm[KH_OFF + (nf*8+g)*F2PAD + kk+tg]);
                    uint32_t bh1 = __float_as_uint(sm[KH_OFF + (nf*8+g)*F2PAD + kk+tg+4]);
                    uint32_t bl0 = __float_as_uint(sm[KL_OFF + (nf*8+g)*F2PAD + kk+tg]);
                    uint32_t bl1 = __float_as_uint(sm[KL_OFF + (nf*8+g)*F2PAD + kk+tg+4]);
                    mma_tf32(s[nf], ah, bh0, bh1);
                    mma_tf32(s[nf], ah, bl0, bl1);
                    mma_tf32(s[nf], al, bh0, bh1);
                }
            }

            // causal mask (only when tile crosses the diagonal for this warp)
            if (kt*64 + 63 > 128*qt + 16*warp) {
                int r0l = 128*qt + m0 + g, r1l = r0l + 8;
                #pragma unroll
                for (int nf = 0; nf < 8; nf++) {
                    int c0 = kt*64 + nf*8 + 2*tg, c1 = c0 + 1;
                    if (c0 > r0l) s[nf][0] = -FLT_MAX;
                    if (c1 > r0l) s[nf][1] = -FLT_MAX;
                    if (c0 > r1l) s[nf][2] = -FLT_MAX;
                    if (c1 > r1l) s[nf][3] = -FLT_MAX;
                }
            }

            // online softmax (rows warp-private; quad shuffles)
            float rm0 = -FLT_MAX, rm1 = -FLT_MAX;
            #pragma unroll
            for (int nf = 0; nf < 8; nf++) {
                rm0 = fmaxf(rm0, fmaxf(s[nf][0], s[nf][1]));
                rm1 = fmaxf(rm1, fmaxf(s[nf][2], s[nf][3]));
            }
            rm0 = fmaxf(rm0, __shfl_xor_sync(0xffffffffu, rm0, 1));
            rm0 = fmaxf(rm0, __shfl_xor_sync(0xffffffffu, rm0, 2));
            rm1 = fmaxf(rm1, __shfl_xor_sync(0xffffffffu, rm1, 1));
            rm1 = fmaxf(rm1, __shfl_xor_sync(0xffffffffu, rm1, 2));
            float mn0 = fmaxf(m_i[0], rm0), mn1 = fmaxf(m_i[1], rm1);
            float fac0 = __expf(m_i[0] - mn0), fac1 = __expf(m_i[1] - mn1);
            m_i[0] = mn0; m_i[1] = mn1;
            float rs0 = 0.f, rs1 = 0.f;
            #pragma unroll
            for (int nf = 0; nf < 8; nf++) {
                s[nf][0] = __expf(s[nf][0] - mn0); rs0 += s[nf][0];
                s[nf][1] = __expf(s[nf][1] - mn0); rs0 += s[nf][1];
                s[nf][2] = __expf(s[nf][2] - mn1); rs1 += s[nf][2];
                s[nf][3] = __expf(s[nf][3] - mn1); rs1 += s[nf][3];
            }
            rs0 += __shfl_xor_sync(0xffffffffu, rs0, 1);
            rs0 += __shfl_xor_sync(0xffffffffu, rs0, 2);
            rs1 += __shfl_xor_sync(0xffffffffu, rs1, 1);
            rs1 += __shfl_xor_sync(0xffffffffu, rs1, 2);
            l_i[0] = l_i[0]*fac0 + rs0;
            l_i[1] = l_i[1]*fac1 + rs1;
            #pragma unroll
            for (int nf = 0; nf < 8; nf++) {
                o[nf][0] *= fac0; o[nf][1] *= fac0;
                o[nf][2] *= fac1; o[nf][3] *= fac1;
            }
        }
        __syncthreads();   // all warps done reading K -> P may overwrite

        if (active) {
            #pragma unroll
            for (int nf = 0; nf < 8; nf++) {
                *(float2*)&Ps[(m0+g)*F2PAD   + nf*8 + 2*tg] = make_float2(s[nf][0], s[nf][1]);
                *(float2*)&Ps[(m0+g+8)*F2PAD + nf*8 + 2*tg] = make_float2(s[nf][2], s[nf][3]);
            }
            __syncwarp();

            // O += P * V (3xTF32; P split on the fly)
            #pragma unroll 2
            for (int kk = 0; kk < 64; kk += 8) {
                float a0 = Ps[(m0+g)*F2PAD   + kk+tg];
                float a1 = Ps[(m0+g+8)*F2PAD + kk+tg];
                float a2 = Ps[(m0+g)*F2PAD   + kk+tg+4];
                float a3 = Ps[(m0+g+8)*F2PAD + kk+tg+4];
                uint32_t ah[4], al[4];
                ah[0] = f2tf32(a0); al[0] = f2tf32(a0 - __uint_as_float(ah[0]));
                ah[1] = f2tf32(a1); al[1] = f2tf32(a1 - __uint_as_float(ah[1]));
                ah[2] = f2tf32(a2); al[2] = f2tf32(a2 - __uint_as_float(ah[2]));
                ah[3] = f2tf32(a3); al[3] = f2tf32(a3 - __uint_as_float(ah[3]));
                #pragma unroll
                for (int nf = 0; nf < 8; nf++) {
                    uint32_t bh0 = __float_as_uint(sm[VH_OFF + (kk+tg)*V2PAD   + nf*8+g]);
                    uint32_t bh1 = __float_as_uint(sm[VH_OFF + (kk+tg+4)*V2PAD + nf*8+g]);
                    uint32_t bl0 = __float_as_uint(sm[VL_OFF + (kk+tg)*V2PAD   + nf*8+g]);
                    uint32_t bl1 = __float_as_uint(sm[VL_OFF + (kk+tg+4)*V2PAD + nf*8+g]);
                    mma_tf32(o[nf], ah, bh0, bh1);
                    mma_tf32(o[nf], ah, bl0, bl1);
                    mma_tf32(o[nf], al, bh0, bh1);
                }
            }
        }
    }

    // finalize
    float inv0 = 1.0f / l_i[0], inv1 = 1.0f / l_i[1];
    size_t row = (size_t)b*SEQ + qt*128 + m0 + g;
    float* dst0 = O + row*QDIM + h*64;
    float* dst1 = dst0 + (size_t)8*QDIM;
    #pragma unroll
    for (int nf = 0; nf < 8; nf++) {
        *(float2*)&dst0[nf*8 + 2*tg] = make_float2(o[nf][0]*inv0, o[nf][1]*inv0);
        *(float2*)&dst1[nf*8 + 2*tg] = make_float2(o[nf][2]*inv1, o[nf][3]*inv1);
    }
}

// ---------------------------------------------------------------------------
extern "C" void kernel_launch(void* const* d_in, const int* in_sizes, int n_in,
                              void* d_out, int out_size) {
    (void)in_sizes; (void)n_in; (void)out_size;
    const float* x  = (const float*)d_in[0];
    const float* wq = (const float*)d_in[1];
    const float* wk = (const float*)d_in[2];
    const float* wv = (const float*)d_in[3];
    const float* wo = (const float*)d_in[4];
    float* out = (float*)d_out;

    float* Ap;
    cudaGetSymbolAddress((void**)&Ap, g_A);

    static int attr_set = 0;
    if (!attr_set) {
        cudaFuncSetAttribute(flash2, cudaFuncAttributeMaxDynamicSharedMemorySize, FL2_SMEM);
        cudaFuncSetAttribute(qkv_kernel, cudaFuncAttributeMaxDynamicSharedMemorySize, GEMM_SMEM);
        cudaFuncSetAttribute(outproj_kernel, cudaFuncAttributeMaxDynamicSharedMemorySize, GEMM_SMEM);
        attr_set = 1;
    }

    rope_table_kernel<<<(SEQ*32 + 255)/256, 256>>>();

    qkv_kernel<<<dim3(24, TOKENS/128), 256, GEMM_SMEM>>>(x, wq, wk, wv);

    flash2<<<dim3(SEQ/128, BATCH*NH), 256, FL2_SMEM>>>(Ap);

    outproj_kernel<<<dim3(DMODEL/128, TOKENS/128), 256, GEMM_SMEM>>>(wo, out);
}

// round 9
// speedup vs baseline: 1.2579x; 1.0605x over previous
#include <cuda_runtime.h>
#include <cuda_bf16.h>
#include <math.h>
#include <float.h>
#include <stdint.h>

// Problem constants
#define BATCH 2
#define SEQ   2048
#define DMODEL 2048
#define NH    32
#define NKV   8
#define REP   4
#define HD    64
#define TOKENS (BATCH*SEQ)   // 4096
#define QDIM  (NH*HD)        // 2048
#define KVDIM (NKV*HD)       // 512

// Scratch (device globals: allocation-free)
__device__ float g_Qh[TOKENS*QDIM],  g_Ql[TOKENS*QDIM];    // pre-scaled tf32 split Q
__device__ float g_Kh[TOKENS*KVDIM], g_Kl[TOKENS*KVDIM];
__device__ float g_Vh[TOKENS*KVDIM], g_Vl[TOKENS*KVDIM];
__device__ float g_A[TOKENS*QDIM];                          // flash output (fp32)
// tf32 pre-rounded GEMM operands
__device__ float g_xr[TOKENS*DMODEL];
__device__ float g_wqr[DMODEL*QDIM];
__device__ float g_wkr[DMODEL*KVDIM];
__device__ float g_wvr[DMODEL*KVDIM];
__device__ float g_wor[QDIM*DMODEL];
__device__ float g_Ar[TOKENS*QDIM];
__device__ float g_cos[SEQ*(HD/2)];
__device__ float g_sin[SEQ*(HD/2)];

__device__ __forceinline__ uint32_t f2tf32(float x) {
    uint32_t r;
    asm("cvt.rna.tf32.f32 %0, %1;" : "=r"(r) : "f"(x));
    return r;
}
__device__ __forceinline__ float tf32f(float x) {
    return __uint_as_float(f2tf32(x));
}
__device__ __forceinline__ void mma_tf32(float* c, const uint32_t* a, uint32_t b0, uint32_t b1) {
    asm volatile("mma.sync.aligned.m16n8k8.row.col.f32.tf32.tf32.f32 "
                 "{%0,%1,%2,%3}, {%4,%5,%6,%7}, {%8,%9}, {%0,%1,%2,%3};"
                 : "+f"(c[0]), "+f"(c[1]), "+f"(c[2]), "+f"(c[3])
                 : "r"(a[0]), "r"(a[1]), "r"(a[2]), "r"(a[3]), "r"(b0), "r"(b1));
}
__device__ __forceinline__ void cp_async16(void* smem_dst, const void* gmem_src) {
    uint32_t s = (uint32_t)__cvta_generic_to_shared(smem_dst);
    asm volatile("cp.async.cg.shared.global [%0], [%1], 16;" :: "r"(s), "l"(gmem_src));
}
__device__ __forceinline__ void cp_commit() {
    asm volatile("cp.async.commit_group;");
}
template<int N> __device__ __forceinline__ void cp_wait() {
    asm volatile("cp.async.wait_group %0;" :: "n"(N));
}

// ---------------------------------------------------------------------------
// tf32 pre-round (bit-identical to cvt.rna in the old inner loop)
// ---------------------------------------------------------------------------
__global__ void round_kernel(const float* __restrict__ in, float* __restrict__ out, int n4) {
    int i = blockIdx.x * blockDim.x + threadIdx.x;
    if (i >= n4) return;
    float4 v = *(const float4*)(in + i*4);
    v.x = tf32f(v.x); v.y = tf32f(v.y); v.z = tf32f(v.z); v.w = tf32f(v.w);
    *(float4*)(out + i*4) = v;
}

// ---------------------------------------------------------------------------
// RoPE tables
// ---------------------------------------------------------------------------
__global__ void rope_table_kernel() {
    int idx = blockIdx.x * blockDim.x + threadIdx.x;
    if (idx >= SEQ*(HD/2)) return;
    int pos = idx >> 5;
    int i   = idx & 31;
    double expo = (2.0 * i) / 64.0;
    float invf = (float)(1.0 / pow(10000.0, expo));
    float fr = (float)pos * invf;
    double a = (double)fr;
    g_cos[idx] = (float)cos(a);
    g_sin[idx] = (float)sin(a);
}

// ---------------------------------------------------------------------------
// Pipelined tf32 GEMM body; operands pre-rounded to tf32 in gmem (no cvt in loop).
//   mode bit0: RoPE   bit1: scale 0.125   bit2: split into (Ch, Cl) tf32 hi/lo
// ---------------------------------------------------------------------------
#define GK 2048
#define NSTG 3
#define APITCH 20
#define BPITCH 136
#define ASTG (128*APITCH)
#define BSTG (16*BPITCH)
#define GEMM_SMEM (NSTG*(ASTG+BSTG)*4)   // 56832 B

__device__ __forceinline__ void gemm_body(const float* __restrict__ A,
                                          const float* __restrict__ B,
                                          float* __restrict__ Ch,
                                          float* __restrict__ Cl,
                                          int N, int by, int cb, int mode) {
    extern __shared__ float sm[];
    float* As = sm;
    float* Bs = sm + NSTG*ASTG;

    int tid  = threadIdx.x;
    int lane = tid & 31, warp = tid >> 5;
    int wm = warp & 3, wn = warp >> 2;
    int m_warp = wm * 32, n_warp = wn * 64;
    int g  = lane >> 2;
    int tg = lane & 3;

    const float* Ablk = A + (size_t)by * 128 * GK;
    const float* Bblk = B + (size_t)cb * 128;

    int a_r0 = tid >> 1, a_k0 = (tid & 1) * 8;
    int b_r0 = tid >> 4, b_n0 = (tid & 15) * 8;

    float acc[2][8][4];
    #pragma unroll
    for (int mi = 0; mi < 2; mi++)
        #pragma unroll
        for (int ni = 0; ni < 8; ni++)
            #pragma unroll
            for (int c = 0; c < 4; c++) acc[mi][ni][c] = 0.f;

    #pragma unroll
    for (int s = 0; s < NSTG-1; s++) {
        int k0 = s * 16;
        float* as = As + s*ASTG;
        float* bs = Bs + s*BSTG;
        cp_async16(&as[a_r0*APITCH + a_k0],     &Ablk[(size_t)a_r0*GK + k0 + a_k0]);
        cp_async16(&as[a_r0*APITCH + a_k0 + 4], &Ablk[(size_t)a_r0*GK + k0 + a_k0 + 4]);
        cp_async16(&bs[b_r0*BPITCH + b_n0],     &Bblk[(size_t)(k0+b_r0)*N + b_n0]);
        cp_async16(&bs[b_r0*BPITCH + b_n0 + 4], &Bblk[(size_t)(k0+b_r0)*N + b_n0 + 4]);
        cp_commit();
    }

    const int NITER = GK / 16;
    int s = 0;
    for (int it = 0; it < NITER; it++) {
        cp_wait<NSTG-2>();
        __syncthreads();

        int kpre = (it + NSTG - 1) * 16;
        if (kpre < GK) {
            int sp = (it + NSTG - 1) % NSTG;
            float* as = As + sp*ASTG;
            float* bs = Bs + sp*BSTG;
            cp_async16(&as[a_r0*APITCH + a_k0],     &Ablk[(size_t)a_r0*GK + kpre + a_k0]);
            cp_async16(&as[a_r0*APITCH + a_k0 + 4], &Ablk[(size_t)a_r0*GK + kpre + a_k0 + 4]);
            cp_async16(&bs[b_r0*BPITCH + b_n0],     &Bblk[(size_t)(kpre+b_r0)*N + b_n0]);
            cp_async16(&bs[b_r0*BPITCH + b_n0 + 4], &Bblk[(size_t)(kpre+b_r0)*N + b_n0 + 4]);
        }
        cp_commit();

        const float* as = As + s*ASTG;
        const float* bs = Bs + s*BSTG;
        #pragma unroll
        for (int kk = 0; kk < 16; kk += 8) {
            uint32_t afr[2][4];
            #pragma unroll
            for (int mi = 0; mi < 2; mi++) {
                int mb = m_warp + mi*16;
                afr[mi][0] = __float_as_uint(as[(mb+g)*APITCH   + kk+tg]);
                afr[mi][1] = __float_as_uint(as[(mb+g+8)*APITCH + kk+tg]);
                afr[mi][2] = __float_as_uint(as[(mb+g)*APITCH   + kk+tg+4]);
                afr[mi][3] = __float_as_uint(as[(mb+g+8)*APITCH + kk+tg+4]);
            }
            uint32_t bfr[8][2];
            #pragma unroll
            for (int ni = 0; ni < 8; ni++) {
                int nb = n_warp + ni*8;
                bfr[ni][0] = __float_as_uint(bs[(kk+tg)*BPITCH   + nb + g]);
                bfr[ni][1] = __float_as_uint(bs[(kk+tg+4)*BPITCH + nb + g]);
            }
            #pragma unroll
            for (int mi = 0; mi < 2; mi++)
                #pragma unroll
                for (int ni = 0; ni < 8; ni++)
                    mma_tf32(acc[mi][ni], afr[mi], bfr[ni][0], bfr[ni][1]);
        }
        s = (s + 1) % NSTG;
    }

    // ---- fused RoPE (warp tile spans exactly one head) ----
    if (mode & 1) {
        #pragma unroll
        for (int mi = 0; mi < 2; mi++) {
            int ra = by*128 + m_warp + mi*16 + g;
            int pa = ra & (SEQ-1);
            int pb = (ra + 8) & (SEQ-1);
            #pragma unroll
            for (int ni = 0; ni < 4; ni++) {
                int i0 = ni*8 + tg*2;
                float ca0 = g_cos[pa*32 + i0],   sa0 = g_sin[pa*32 + i0];
                float ca1 = g_cos[pa*32 + i0+1], sa1 = g_sin[pa*32 + i0+1];
                float cb0 = g_cos[pb*32 + i0],   sb0 = g_sin[pb*32 + i0];
                float cb1 = g_cos[pb*32 + i0+1], sb1 = g_sin[pb*32 + i0+1];
                float x1, x2;
                x1 = acc[mi][ni][0]; x2 = acc[mi][ni+4][0];
                acc[mi][ni][0] = x1*ca0 - x2*sa0; acc[mi][ni+4][0] = x1*sa0 + x2*ca0;
                x1 = acc[mi][ni][1]; x2 = acc[mi][ni+4][1];
                acc[mi][ni][1] = x1*ca1 - x2*sa1; acc[mi][ni+4][1] = x1*sa1 + x2*ca1;
                x1 = acc[mi][ni][2]; x2 = acc[mi][ni+4][2];
                acc[mi][ni][2] = x1*cb0 - x2*sb0; acc[mi][ni+4][2] = x1*sb0 + x2*cb0;
                x1 = acc[mi][ni][3]; x2 = acc[mi][ni+4][3];
                acc[mi][ni][3] = x1*cb1 - x2*sb1; acc[mi][ni+4][3] = x1*sb1 + x2*cb1;
            }
        }
    }

    float mul = (mode & 2) ? 0.125f : 1.0f;
    size_t rowbase = (size_t)by * 128 + m_warp + g;
    int colbase = cb * 128 + n_warp + tg*2;
    if (mode & 4) {
        #pragma unroll
        for (int mi = 0; mi < 2; mi++) {
            size_t r0 = rowbase + mi*16;
            #pragma unroll
            for (int ni = 0; ni < 8; ni++) {
                int c = colbase + ni*8;
                float v0 = acc[mi][ni][0]*mul, v1 = acc[mi][ni][1]*mul;
                float v2 = acc[mi][ni][2]*mul, v3 = acc[mi][ni][3]*mul;
                float h0 = tf32f(v0), h1 = tf32f(v1), h2 = tf32f(v2), h3 = tf32f(v3);
                *(float2*)&Ch[r0*N + c]     = make_float2(h0, h1);
                *(float2*)&Ch[(r0+8)*N + c] = make_float2(h2, h3);
                *(float2*)&Cl[r0*N + c]     = make_float2(tf32f(v0-h0), tf32f(v1-h1));
                *(float2*)&Cl[(r0+8)*N + c] = make_float2(tf32f(v2-h2), tf32f(v3-h3));
            }
        }
    } else {
        #pragma unroll
        for (int mi = 0; mi < 2; mi++) {
            size_t r0 = rowbase + mi*16;
            #pragma unroll
            for (int ni = 0; ni < 8; ni++) {
                int c = colbase + ni*8;
                *(float2*)&Ch[r0*N + c]     = make_float2(acc[mi][ni][0], acc[mi][ni][1]);
                *(float2*)&Ch[(r0+8)*N + c] = make_float2(acc[mi][ni][2], acc[mi][ni][3]);
            }
        }
    }
}

// Fused QKV projection + RoPE + tf32-split. grid=(24,32)
__global__ __launch_bounds__(256) void qkv_kernel() {
    int bx = blockIdx.x;
    const float* B; float *Ch, *Cl; int N, cb, mode;
    if (bx < 16)      { B = g_wqr; Ch = g_Qh; Cl = g_Ql; N = QDIM;  cb = bx;      mode = 7; }
    else if (bx < 20) { B = g_wkr; Ch = g_Kh; Cl = g_Kl; N = KVDIM; cb = bx - 16; mode = 5; }
    else              { B = g_wvr; Ch = g_Vh; Cl = g_Vl; N = KVDIM; cb = bx - 20; mode = 4; }
    gemm_body(g_xr, B, Ch, Cl, N, blockIdx.y, cb, mode);
}

// Output projection. grid=(16,32)
__global__ __launch_bounds__(256) void outproj_kernel(float* __restrict__ out) {
    gemm_body(g_Ar, g_wor, out, nullptr, DMODEL, blockIdx.y, blockIdx.x, 0);
}

// ---------------------------------------------------------------------------
// Flash attention v3: 3xTF32, q-tile 128, 256 threads = 8 warps, double-buffered
// K/V tiles (cp.async overlap with compute). P aliases current-stage K region.
// ---------------------------------------------------------------------------
#define F2PAD 68
#define V2PAD 72
#define QH_O 0
#define QL_O (128*F2PAD)
#define STAGE_BASE (2*128*F2PAD)                  // 17408 floats
#define SSTRIDE (2*64*F2PAD + 2*64*V2PAD)         // 17920 floats
#define KH_O(s) (STAGE_BASE + (s)*SSTRIDE)
#define KL_O(s) (KH_O(s) + 64*F2PAD)
#define VH_O(s) (KH_O(s) + 2*64*F2PAD)
#define VL_O(s) (VH_O(s) + 64*V2PAD)
#define FL3_SMEM ((STAGE_BASE + 2*SSTRIDE)*4)     // 212992 B

__global__ __launch_bounds__(256) void flash3(float* __restrict__ O) {
    extern __shared__ float sm[];

    int qt = blockIdx.x;                 // 0..15
    int bh = blockIdx.y;
    int b = bh >> 5, h = bh & 31, gkv = h >> 2;
    int tid = threadIdx.x;
    int lane = tid & 31, warp = tid >> 5;
    int g = lane >> 2, tg = lane & 3;
    int m0 = warp * 16;

    const float* Qhb = g_Qh + ((size_t)b*SEQ + qt*128)*QDIM + h*64;
    const float* Qlb = g_Ql + ((size_t)b*SEQ + qt*128)*QDIM + h*64;
    const float* Khb = g_Kh + (size_t)b*SEQ*KVDIM + gkv*64;
    const float* Klb = g_Kl + (size_t)b*SEQ*KVDIM + gkv*64;
    const float* Vhb = g_Vh + (size_t)b*SEQ*KVDIM + gkv*64;
    const float* Vlb = g_Vl + (size_t)b*SEQ*KVDIM + gkv*64;

    int ld_r = tid >> 4, ld_q = (tid & 15) * 4;   // K/V loads: 16 rows/pass x 16 cols

    // prologue: Q tile + K0/V0, one group
    #pragma unroll
    for (int j = 0; j < 8; j++) {
        int ci = tid + j*256;
        int r = ci >> 4, q = ci & 15;
        cp_async16(&sm[QH_O + r*F2PAD + q*4], &Qhb[(size_t)r*QDIM + q*4]);
        cp_async16(&sm[QL_O + r*F2PAD + q*4], &Qlb[(size_t)r*QDIM + q*4]);
    }
    #pragma unroll
    for (int j = 0; j < 4; j++) {
        int r = ld_r + j*16;
        size_t go = (size_t)r*KVDIM + ld_q;
        cp_async16(&sm[KH_O(0) + r*F2PAD + ld_q], Khb + go);
        cp_async16(&sm[KL_O(0) + r*F2PAD + ld_q], Klb + go);
        cp_async16(&sm[VH_O(0) + r*V2PAD + ld_q], Vhb + go);
        cp_async16(&sm[VL_O(0) + r*V2PAD + ld_q], Vlb + go);
    }
    cp_commit();

    float m_i[2] = {-FLT_MAX, -FLT_MAX};
    float l_i[2] = {0.f, 0.f};
    float o[8][4];
    #pragma unroll
    for (int nf = 0; nf < 8; nf++)
        #pragma unroll
        for (int c = 0; c < 4; c++) o[nf][c] = 0.f;

    int ktmax = (128*qt + 16*warp + 15) >> 6;
    int kt_end = 2*qt + 1;

    for (int kt = 0; kt <= kt_end; kt++) {
        int st = kt & 1;
        // issue loads for kt+1 into the other stage (its P/V consumers finished
        // last iteration; trailing __syncthreads guarantees safety)
        if (kt < kt_end) {
            int nx = st ^ 1;
            #pragma unroll
            for (int j = 0; j < 4; j++) {
                int r = ld_r + j*16;
                size_t go = (size_t)((kt+1)*64 + r)*KVDIM + ld_q;
                cp_async16(&sm[KH_O(nx) + r*F2PAD + ld_q], Khb + go);
                cp_async16(&sm[KL_O(nx) + r*F2PAD + ld_q], Klb + go);
                cp_async16(&sm[VH_O(nx) + r*V2PAD + ld_q], Vhb + go);
                cp_async16(&sm[VL_O(nx) + r*V2PAD + ld_q], Vlb + go);
            }
        }
        cp_commit();
        cp_wait<1>();      // current stage (kt) ready; next-stage loads in flight
        __syncthreads();

        bool active = (kt <= ktmax);
        float* Ps = sm + KH_O(st);
        float s[8][4];
        if (active) {
            #pragma unroll
            for (int nf = 0; nf < 8; nf++)
                #pragma unroll
                for (int c = 0; c < 4; c++) s[nf][c] = 0.f;

            #pragma unroll 2
            for (int kk = 0; kk < 64; kk += 8) {
                uint32_t ah[4], al[4];
                ah[0] = __float_as_uint(sm[QH_O + (m0+g)*F2PAD   + kk+tg]);
                ah[1] = __float_as_uint(sm[QH_O + (m0+g+8)*F2PAD + kk+tg]);
                ah[2] = __float_as_uint(sm[QH_O + (m0+g)*F2PAD   + kk+tg+4]);
                ah[3] = __float_as_uint(sm[QH_O + (m0+g+8)*F2PAD + kk+tg+4]);
                al[0] = __float_as_uint(sm[QL_O + (m0+g)*F2PAD   + kk+tg]);
                al[1] = __float_as_uint(sm[QL_O + (m0+g+8)*F2PAD + kk+tg]);
                al[2] = __float_as_uint(sm[QL_O + (m0+g)*F2PAD   + kk+tg+4]);
                al[3] = __float_as_uint(sm[QL_O + (m0+g+8)*F2PAD + kk+tg+4]);
                #pragma unroll
                for (int nf = 0; nf < 8; nf++) {
                    uint32_t bh0 = __float_as_uint(sm[KH_O(st) + (nf*8+g)*F2PAD + kk+tg]);
                    uint32_t bh1 = __float_as_uint(sm[KH_O(st) + (nf*8+g)*F2PAD + kk+tg+4]);
                    uint32_t bl0 = __float_as_uint(sm[KL_O(st) + (nf*8+g)*F2PAD + kk+tg]);
                    uint32_t bl1 = __float_as_uint(sm[KL_O(st) + (nf*8+g)*F2PAD + kk+tg+4]);
                    mma_tf32(s[nf], ah, bh0, bh1);
                    mma_tf32(s[nf], ah, bl0, bl1);
                    mma_tf32(s[nf], al, bh0, bh1);
                }
            }

            if (kt*64 + 63 > 128*qt + 16*warp) {
                int r0l = 128*qt + m0 + g, r1l = r0l + 8;
                #pragma unroll
                for (int nf = 0; nf < 8; nf++) {
                    int c0 = kt*64 + nf*8 + 2*tg, c1 = c0 + 1;
                    if (c0 > r0l) s[nf][0] = -FLT_MAX;
                    if (c1 > r0l) s[nf][1] = -FLT_MAX;
                    if (c0 > r1l) s[nf][2] = -FLT_MAX;
                    if (c1 > r1l) s[nf][3] = -FLT_MAX;
                }
            }

            float rm0 = -FLT_MAX, rm1 = -FLT_MAX;
            #pragma unroll
            for (int nf = 0; nf < 8; nf++) {
                rm0 = fmaxf(rm0, fmaxf(s[nf][0], s[nf][1]));
                rm1 = fmaxf(rm1, fmaxf(s[nf][2], s[nf][3]));
            }
            rm0 = fmaxf(rm0, __shfl_xor_sync(0xffffffffu, rm0, 1));
            rm0 = fmaxf(rm0, __shfl_xor_sync(0xffffffffu, rm0, 2));
            rm1 = fmaxf(rm1, __shfl_xor_sync(0xffffffffu, rm1, 1));
            rm1 = fmaxf(rm1, __shfl_xor_sync(0xffffffffu, rm1, 2));
            float mn0 = fmaxf(m_i[0], rm0), mn1 = fmaxf(m_i[1], rm1);
            float fac0 = __expf(m_i[0] - mn0), fac1 = __expf(m_i[1] - mn1);
            m_i[0] = mn0; m_i[1] = mn1;
            float rs0 = 0.f, rs1 = 0.f;
            #pragma unroll
            for (int nf = 0; nf < 8; nf++) {
                s[nf][0] = __expf(s[nf][0] - mn0); rs0 += s[nf][0];
                s[nf][1] = __expf(s[nf][1] - mn0); rs0 += s[nf][1];
                s[nf][2] = __expf(s[nf][2] - mn1); rs1 += s[nf][2];
                s[nf][3] = __expf(s[nf][3] - mn1); rs1 += s[nf][3];
            }
            rs0 += __shfl_xor_sync(0xffffffffu, rs0, 1);
            rs0 += __shfl_xor_sync(0xffffffffu, rs0, 2);
            rs1 += __shfl_xor_sync(0xffffffffu, rs1, 1);
            rs1 += __shfl_xor_sync(0xffffffffu, rs1, 2);
            l_i[0] = l_i[0]*fac0 + rs0;
            l_i[1] = l_i[1]*fac1 + rs1;
            #pragma unroll
            for (int nf = 0; nf < 8; nf++) {
                o[nf][0] *= fac0; o[nf][1] *= fac0;
                o[nf][2] *= fac1; o[nf][3] *= fac1;
            }
        }
        __syncthreads();   // all warps done reading K[st] -> P may overwrite it

        if (active) {
            #pragma unroll
            for (int nf = 0; nf < 8; nf++) {
                *(float2*)&Ps[(m0+g)*F2PAD   + nf*8 + 2*tg] = make_float2(s[nf][0], s[nf][1]);
                *(float2*)&Ps[(m0+g+8)*F2PAD + nf*8 + 2*tg] = make_float2(s[nf][2], s[nf][3]);
            }
            __syncwarp();

            #pragma unroll 2
            for (int kk = 0; kk < 64; kk += 8) {
                float a0 = Ps[(m0+g)*F2PAD   + kk+tg];
                float a1 = Ps[(m0+g+8)*F2PAD + kk+tg];
                float a2 = Ps[(m0+g)*F2PAD   + kk+tg+4];
                float a3 = Ps[(m0+g+8)*F2PAD + kk+tg+4];
                uint32_t ah[4], al[4];
                ah[0] = f2tf32(a0); al[0] = f2tf32(a0 - __uint_as_float(ah[0]));
                ah[1] = f2tf32(a1); al[1] = f2tf32(a1 - __uint_as_float(ah[1]));
                ah[2] = f2tf32(a2); al[2] = f2tf32(a2 - __uint_as_float(ah[2]));
                ah[3] = f2tf32(a3); al[3] = f2tf32(a3 - __uint_as_float(ah[3]));
                #pragma unroll
                for (int nf = 0; nf < 8; nf++) {
                    uint32_t bh0 = __float_as_uint(sm[VH_O(st) + (kk+tg)*V2PAD   + nf*8+g]);
                    uint32_t bh1 = __float_as_uint(sm[VH_O(st) + (kk+tg+4)*V2PAD + nf*8+g]);
                    uint32_t bl0 = __float_as_uint(sm[VL_O(st) + (kk+tg)*V2PAD   + nf*8+g]);
                    uint32_t bl1 = __float_as_uint(sm[VL_O(st) + (kk+tg+4)*V2PAD + nf*8+g]);
                    mma_tf32(o[nf], ah, bh0, bh1);
                    mma_tf32(o[nf], ah, bl0, bl1);
                    mma_tf32(o[nf], al, bh0, bh1);
                }
            }
        }
        __syncthreads();   // P/V[st] fully consumed before next iter loads into st
    }

    float inv0 = 1.0f / l_i[0], inv1 = 1.0f / l_i[1];
    size_t row = (size_t)b*SEQ + qt*128 + m0 + g;
    float* dst0 = O + row*QDIM + h*64;
    float* dst1 = dst0 + (size_t)8*QDIM;
    #pragma unroll
    for (int nf = 0; nf < 8; nf++) {
        *(float2*)&dst0[nf*8 + 2*tg] = make_float2(o[nf][0]*inv0, o[nf][1]*inv0);
        *(float2*)&dst1[nf*8 + 2*tg] = make_float2(o[nf][2]*inv1, o[nf][3]*inv1);
    }
}

// ---------------------------------------------------------------------------
extern "C" void kernel_launch(void* const* d_in, const int* in_sizes, int n_in,
                              void* d_out, int out_size) {
    (void)in_sizes; (void)n_in; (void)out_size;
    const float* x  = (const float*)d_in[0];
    const float* wq = (const float*)d_in[1];
    const float* wk = (const float*)d_in[2];
    const float* wv = (const float*)d_in[3];
    const float* wo = (const float*)d_in[4];
    float* out = (float*)d_out;

    float *Ap, *Arp, *xr, *wqr, *wkr, *wvr, *wor;
    cudaGetSymbolAddress((void**)&Ap,  g_A);
    cudaGetSymbolAddress((void**)&Arp, g_Ar);
    cudaGetSymbolAddress((void**)&xr,  g_xr);
    cudaGetSymbolAddress((void**)&wqr, g_wqr);
    cudaGetSymbolAddress((void**)&wkr, g_wkr);
    cudaGetSymbolAddress((void**)&wvr, g_wvr);
    cudaGetSymbolAddress((void**)&wor, g_wor);

    static int attr_set = 0;
    if (!attr_set) {
        cudaFuncSetAttribute(flash3, cudaFuncAttributeMaxDynamicSharedMemorySize, FL3_SMEM);
        cudaFuncSetAttribute(qkv_kernel, cudaFuncAttributeMaxDynamicSharedMemorySize, GEMM_SMEM);
        cudaFuncSetAttribute(outproj_kernel, cudaFuncAttributeMaxDynamicSharedMemorySize, GEMM_SMEM);
        attr_set = 1;
    }

    rope_table_kernel<<<(SEQ*32 + 255)/256, 256>>>();

    round_kernel<<<(TOKENS*DMODEL/4 + 255)/256, 256>>>(x,  xr,  TOKENS*DMODEL/4);
    round_kernel<<<(DMODEL*QDIM/4  + 255)/256, 256>>>(wq, wqr, DMODEL*QDIM/4);
    round_kernel<<<(DMODEL*KVDIM/4 + 255)/256, 256>>>(wk, wkr, DMODEL*KVDIM/4);
    round_kernel<<<(DMODEL*KVDIM/4 + 255)/256, 256>>>(wv, wvr, DMODEL*KVDIM/4);
    round_kernel<<<(QDIM*DMODEL/4  + 255)/256, 256>>>(wo, wor, QDIM*DMODEL/4);

    qkv_kernel<<<dim3(24, TOKENS/128), 256, GEMM_SMEM>>>();

    flash3<<<dim3(SEQ/128, BATCH*NH), 256, FL3_SMEM>>>(Ap);

    round_kernel<<<(TOKENS*QDIM/4 + 255)/256, 256>>>(Ap, Arp, TOKENS*QDIM/4);

    outproj_kernel<<<dim3(DMODEL/128, TOKENS/128), 256, GEMM_SMEM>>>(out);
}

// round 13
// speedup vs baseline: 1.5615x; 1.2414x over previous
#include <cuda_runtime.h>
#include <cuda_bf16.h>
#include <math.h>
#include <float.h>
#include <stdint.h>

// Problem constants
#define BATCH 2
#define SEQ   2048
#define DMODEL 2048
#define NH    32
#define NKV   8
#define REP   4
#define HD    64
#define TOKENS (BATCH*SEQ)   // 4096
#define QDIM  (NH*HD)        // 2048
#define KVDIM (NKV*HD)       // 512

// Scratch (device globals: allocation-free)
__device__ __nv_bfloat16 g_Qhb[TOKENS*QDIM],  g_Qlb[TOKENS*QDIM];   // pre-scaled bf16 split Q
__device__ __nv_bfloat16 g_Khb[TOKENS*KVDIM], g_Klb[TOKENS*KVDIM];
__device__ __nv_bfloat16 g_Vhb[TOKENS*KVDIM], g_Vlb[TOKENS*KVDIM];
__device__ float g_A[TOKENS*QDIM];          // flash output (fp32)
// tf32 pre-rounded GEMM operands
__device__ float g_xr[TOKENS*DMODEL];
__device__ float g_wqr[DMODEL*QDIM];
__device__ float g_wkr[DMODEL*KVDIM];
__device__ float g_wvr[DMODEL*KVDIM];
__device__ float g_wor[QDIM*DMODEL];
__device__ float g_Ar[TOKENS*QDIM];
__device__ float g_cos[SEQ*(HD/2)];
__device__ float g_sin[SEQ*(HD/2)];

__device__ __forceinline__ uint32_t f2tf32(float x) {
    uint32_t r;
    asm("cvt.rna.tf32.f32 %0, %1;" : "=r"(r) : "f"(x));
    return r;
}
__device__ __forceinline__ float tf32f(float x) {
    return __uint_as_float(f2tf32(x));
}
__device__ __forceinline__ void mma_tf32(float* c, const uint32_t* a, uint32_t b0, uint32_t b1) {
    asm volatile("mma.sync.aligned.m16n8k8.row.col.f32.tf32.tf32.f32 "
                 "{%0,%1,%2,%3}, {%4,%5,%6,%7}, {%8,%9}, {%0,%1,%2,%3};"
                 : "+f"(c[0]), "+f"(c[1]), "+f"(c[2]), "+f"(c[3])
                 : "r"(a[0]), "r"(a[1]), "r"(a[2]), "r"(a[3]), "r"(b0), "r"(b1));
}
__device__ __forceinline__ void mma_bf16(float* c, const uint32_t* a, uint32_t b0, uint32_t b1) {
    asm volatile("mma.sync.aligned.m16n8k16.row.col.f32.bf16.bf16.f32 "
                 "{%0,%1,%2,%3}, {%4,%5,%6,%7}, {%8,%9}, {%0,%1,%2,%3};"
                 : "+f"(c[0]), "+f"(c[1]), "+f"(c[2]), "+f"(c[3])
                 : "r"(a[0]), "r"(a[1]), "r"(a[2]), "r"(a[3]), "r"(b0), "r"(b1));
}
__device__ __forceinline__ void ldmx4(uint32_t* r, uint32_t addr) {
    asm volatile("ldmatrix.sync.aligned.m8n8.x4.shared.b16 {%0,%1,%2,%3}, [%4];"
                 : "=r"(r[0]), "=r"(r[1]), "=r"(r[2]), "=r"(r[3]) : "r"(addr));
}
__device__ __forceinline__ void ldmx4t(uint32_t* r, uint32_t addr) {
    asm volatile("ldmatrix.sync.aligned.m8n8.x4.trans.shared.b16 {%0,%1,%2,%3}, [%4];"
                 : "=r"(r[0]), "=r"(r[1]), "=r"(r[2]), "=r"(r[3]) : "r"(addr));
}
__device__ __forceinline__ void cp_async16(void* smem_dst, const void* gmem_src) {
    uint32_t s = (uint32_t)__cvta_generic_to_shared(smem_dst);
    asm volatile("cp.async.cg.shared.global [%0], [%1], 16;" :: "r"(s), "l"(gmem_src));
}
__device__ __forceinline__ void cp_commit() {
    asm volatile("cp.async.commit_group;");
}
template<int N> __device__ __forceinline__ void cp_wait() {
    asm volatile("cp.async.wait_group %0;" :: "n"(N));
}
__device__ __forceinline__ uint32_t pack_bf16(float a, float b, float* ra, float* rb) {
    __nv_bfloat16 ha = __float2bfloat16(a);
    __nv_bfloat16 hb = __float2bfloat16(b);
    *ra = a - __bfloat162float(ha);
    *rb = b - __bfloat162float(hb);
    uint32_t lo = (uint32_t)__bfloat16_as_ushort(ha);
    uint32_t hi = (uint32_t)__bfloat16_as_ushort(hb);
    return lo | (hi << 16);
}

// ---------------------------------------------------------------------------
// tf32 pre-round
// ---------------------------------------------------------------------------
__global__ void round_kernel(const float* __restrict__ in, float* __restrict__ out, int n4) {
    int i = blockIdx.x * blockDim.x + threadIdx.x;
    if (i >= n4) return;
    float4 v = *(const float4*)(in + i*4);
    v.x = tf32f(v.x); v.y = tf32f(v.y); v.z = tf32f(v.z); v.w = tf32f(v.w);
    *(float4*)(out + i*4) = v;
}

// ---------------------------------------------------------------------------
// RoPE tables
// ---------------------------------------------------------------------------
__global__ void rope_table_kernel() {
    int idx = blockIdx.x * blockDim.x + threadIdx.x;
    if (idx >= SEQ*(HD/2)) return;
    int pos = idx >> 5;
    int i   = idx & 31;
    double expo = (2.0 * i) / 64.0;
    float invf = (float)(1.0 / pow(10000.0, expo));
    float fr = (float)pos * invf;
    double a = (double)fr;
    g_cos[idx] = (float)cos(a);
    g_sin[idx] = (float)sin(a);
}

// ---------------------------------------------------------------------------
// Pipelined tf32 GEMM body; operands pre-rounded tf32 in gmem.
//   mode bit0: RoPE   bit1: scale 0.125   bit2: split into bf16 hi/lo (Chb,Clb)
// ---------------------------------------------------------------------------
#define GK 2048
#define NSTG 3
#define APITCH 20
#define BPITCH 136
#define ASTG (128*APITCH)
#define BSTG (16*BPITCH)
#define GEMM_SMEM (NSTG*(ASTG+BSTG)*4)   // 56832 B

__device__ __forceinline__ void gemm_body(const float* __restrict__ A,
                                          const float* __restrict__ B,
                                          float* __restrict__ Cf,
                                          __nv_bfloat16* __restrict__ Chb,
                                          __nv_bfloat16* __restrict__ Clb,
                                          int N, int by, int cb, int mode) {
    extern __shared__ float sm[];
    float* As = sm;
    float* Bs = sm + NSTG*ASTG;

    int tid  = threadIdx.x;
    int lane = tid & 31, warp = tid >> 5;
    int wm = warp & 3, wn = warp >> 2;
    int m_warp = wm * 32, n_warp = wn * 64;
    int g  = lane >> 2;
    int tg = lane & 3;

    const float* Ablk = A + (size_t)by * 128 * GK;
    const float* Bblk = B + (size_t)cb * 128;

    int a_r0 = tid >> 1, a_k0 = (tid & 1) * 8;
    int b_r0 = tid >> 4, b_n0 = (tid & 15) * 8;

    float acc[2][8][4];
    #pragma unroll
    for (int mi = 0; mi < 2; mi++)
        #pragma unroll
        for (int ni = 0; ni < 8; ni++)
            #pragma unroll
            for (int c = 0; c < 4; c++) acc[mi][ni][c] = 0.f;

    #pragma unroll
    for (int s = 0; s < NSTG-1; s++) {
        int k0 = s * 16;
        float* as = As + s*ASTG;
        float* bs = Bs + s*BSTG;
        cp_async16(&as[a_r0*APITCH + a_k0],     &Ablk[(size_t)a_r0*GK + k0 + a_k0]);
        cp_async16(&as[a_r0*APITCH + a_k0 + 4], &Ablk[(size_t)a_r0*GK + k0 + a_k0 + 4]);
        cp_async16(&bs[b_r0*BPITCH + b_n0],     &Bblk[(size_t)(k0+b_r0)*N + b_n0]);
        cp_async16(&bs[b_r0*BPITCH + b_n0 + 4], &Bblk[(size_t)(k0+b_r0)*N + b_n0 + 4]);
        cp_commit();
    }

    const int NITER = GK / 16;
    int s = 0;
    for (int it = 0; it < NITER; it++) {
        cp_wait<NSTG-2>();
        __syncthreads();

        int kpre = (it + NSTG - 1) * 16;
        if (kpre < GK) {
            int sp = (it + NSTG - 1) % NSTG;
            float* as = As + sp*ASTG;
            float* bs = Bs + sp*BSTG;
            cp_async16(&as[a_r0*APITCH + a_k0],     &Ablk[(size_t)a_r0*GK + kpre + a_k0]);
            cp_async16(&as[a_r0*APITCH + a_k0 + 4], &Ablk[(size_t)a_r0*GK + kpre + a_k0 + 4]);
            cp_async16(&bs[b_r0*BPITCH + b_n0],     &Bblk[(size_t)(kpre+b_r0)*N + b_n0]);
            cp_async16(&bs[b_r0*BPITCH + b_n0 + 4], &Bblk[(size_t)(kpre+b_r0)*N + b_n0 + 4]);
        }
        cp_commit();

        const float* as = As + s*ASTG;
        const float* bs = Bs + s*BSTG;
        #pragma unroll
        for (int kk = 0; kk < 16; kk += 8) {
            uint32_t afr[2][4];
            #pragma unroll
            for (int mi = 0; mi < 2; mi++) {
                int mb = m_warp + mi*16;
                afr[mi][0] = __float_as_uint(as[(mb+g)*APITCH   + kk+tg]);
                afr[mi][1] = __float_as_uint(as[(mb+g+8)*APITCH + kk+tg]);
                afr[mi][2] = __float_as_uint(as[(mb+g)*APITCH   + kk+tg+4]);
                afr[mi][3] = __float_as_uint(as[(mb+g+8)*APITCH + kk+tg+4]);
            }
            uint32_t bfr[8][2];
            #pragma unroll
            for (int ni = 0; ni < 8; ni++) {
                int nb = n_warp + ni*8;
                bfr[ni][0] = __float_as_uint(bs[(kk+tg)*BPITCH   + nb + g]);
                bfr[ni][1] = __float_as_uint(bs[(kk+tg+4)*BPITCH + nb + g]);
            }
            #pragma unroll
            for (int mi = 0; mi < 2; mi++)
                #pragma unroll
                for (int ni = 0; ni < 8; ni++)
                    mma_tf32(acc[mi][ni], afr[mi], bfr[ni][0], bfr[ni][1]);
        }
        s = (s + 1) % NSTG;
    }

    // ---- fused RoPE (warp tile spans exactly one head) ----
    if (mode & 1) {
        #pragma unroll
        for (int mi = 0; mi < 2; mi++) {
            int ra = by*128 + m_warp + mi*16 + g;
            int pa = ra & (SEQ-1);
            int pb = (ra + 8) & (SEQ-1);
            #pragma unroll
            for (int ni = 0; ni < 4; ni++) {
                int i0 = ni*8 + tg*2;
                float ca0 = g_cos[pa*32 + i0],   sa0 = g_sin[pa*32 + i0];
                float ca1 = g_cos[pa*32 + i0+1], sa1 = g_sin[pa*32 + i0+1];
                float cb0 = g_cos[pb*32 + i0],   sb0 = g_sin[pb*32 + i0];
                float cb1 = g_cos[pb*32 + i0+1], sb1 = g_sin[pb*32 + i0+1];
                float x1, x2;
                x1 = acc[mi][ni][0]; x2 = acc[mi][ni+4][0];
                acc[mi][ni][0] = x1*ca0 - x2*sa0; acc[mi][ni+4][0] = x1*sa0 + x2*ca0;
                x1 = acc[mi][ni][1]; x2 = acc[mi][ni+4][1];
                acc[mi][ni][1] = x1*ca1 - x2*sa1; acc[mi][ni+4][1] = x1*sa1 + x2*ca1;
                x1 = acc[mi][ni][2]; x2 = acc[mi][ni+4][2];
                acc[mi][ni][2] = x1*cb0 - x2*sb0; acc[mi][ni+4][2] = x1*sb0 + x2*cb0;
                x1 = acc[mi][ni][3]; x2 = acc[mi][ni+4][3];
                acc[mi][ni][3] = x1*cb1 - x2*sb1; acc[mi][ni+4][3] = x1*sb1 + x2*cb1;
            }
        }
    }

    float mul = (mode & 2) ? 0.125f : 1.0f;
    size_t rowbase = (size_t)by * 128 + m_warp + g;
    int colbase = cb * 128 + n_warp + tg*2;
    if (mode & 4) {
        #pragma unroll
        for (int mi = 0; mi < 2; mi++) {
            size_t r0 = rowbase + mi*16;
            #pragma unroll
            for (int ni = 0; ni < 8; ni++) {
                int c = colbase + ni*8;
                float l0, l1, l2, l3;
                uint32_t h01 = pack_bf16(acc[mi][ni][0]*mul, acc[mi][ni][1]*mul, &l0, &l1);
                uint32_t h23 = pack_bf16(acc[mi][ni][2]*mul, acc[mi][ni][3]*mul, &l2, &l3);
                *(uint32_t*)&Chb[r0*N + c]     = h01;
                *(uint32_t*)&Chb[(r0+8)*N + c] = h23;
                float d0, d1;
                *(uint32_t*)&Clb[r0*N + c]     = pack_bf16(l0, l1, &d0, &d1);
                *(uint32_t*)&Clb[(r0+8)*N + c] = pack_bf16(l2, l3, &d0, &d1);
            }
        }
    } else {
        #pragma unroll
        for (int mi = 0; mi < 2; mi++) {
            size_t r0 = rowbase + mi*16;
            #pragma unroll
            for (int ni = 0; ni < 8; ni++) {
                int c = colbase + ni*8;
                *(float2*)&Cf[r0*N + c]     = make_float2(acc[mi][ni][0], acc[mi][ni][1]);
                *(float2*)&Cf[(r0+8)*N + c] = make_float2(acc[mi][ni][2], acc[mi][ni][3]);
            }
        }
    }
}

// Fused QKV projection + RoPE + bf16-split. grid=(24,32)
__global__ __launch_bounds__(256) void qkv_kernel() {
    int bx = blockIdx.x;
    const float* B; __nv_bfloat16 *Ch, *Cl; int N, cb, mode;
    if (bx < 16)      { B = g_wqr; Ch = g_Qhb; Cl = g_Qlb; N = QDIM;  cb = bx;      mode = 7; }
    else if (bx < 20) { B = g_wkr; Ch = g_Khb; Cl = g_Klb; N = KVDIM; cb = bx - 16; mode = 5; }
    else              { B = g_wvr; Ch = g_Vhb; Cl = g_Vlb; N = KVDIM; cb = bx - 20; mode = 4; }
    gemm_body(g_xr, B, nullptr, Ch, Cl, N, blockIdx.y, cb, mode);
}

// Output projection. grid=(16,32)
__global__ __launch_bounds__(256) void outproj_kernel(float* __restrict__ out) {
    gemm_body(g_Ar, g_wor, out, nullptr, nullptr, DMODEL, blockIdx.y, blockIdx.x, 0);
}

// ---------------------------------------------------------------------------
// Flash attention v4: 3xBF16 (m16n8k16) + ldmatrix, q-tile 128, 8 warps,
// double-buffered K/V, dedicated P smem. All operands bf16 hi/lo from gmem.
// ---------------------------------------------------------------------------
#define QP 72                                      // bf16 row pitch (144 B)
#define QH_B 0
#define QL_B (128*QP)
#define ST_B (2*128*QP)                            // 18432
#define SS   (4*64*QP)                             // 18432 per stage
#define KH_B(s) (ST_B + (s)*SS)
#define KL_B(s) (KH_B(s) + 64*QP)
#define VH_B(s) (KH_B(s) + 2*64*QP)
#define VL_B(s) (KH_B(s) + 3*64*QP)
#define PH_B (ST_B + 2*SS)                         // 55296
#define PL_B (PH_B + 128*QP)
#define FL4_SMEM ((PL_B + 128*QP)*2)               // 147456 B

__global__ __launch_bounds__(256) void flash4(float* __restrict__ O) {
    extern __shared__ __nv_bfloat16 smh[];

    int qt = blockIdx.x;                 // 0..15
    int bh = blockIdx.y;
    int b = bh >> 5, h = bh & 31, gkv = h >> 2;
    int tid = threadIdx.x;
    int lane = tid & 31, warp = tid >> 5;
    int g = lane >> 2, tg = lane & 3;
    int m0 = warp * 16;

    const __nv_bfloat16* Qhb = g_Qhb + ((size_t)b*SEQ + qt*128)*QDIM + h*64;
    const __nv_bfloat16* Qlb = g_Qlb + ((size_t)b*SEQ + qt*128)*QDIM + h*64;
    const __nv_bfloat16* Khb = g_Khb + (size_t)b*SEQ*KVDIM + gkv*64;
    const __nv_bfloat16* Klb = g_Klb + (size_t)b*SEQ*KVDIM + gkv*64;
    const __nv_bfloat16* Vhb = g_Vhb + (size_t)b*SEQ*KVDIM + gkv*64;
    const __nv_bfloat16* Vlb = g_Vlb + (size_t)b*SEQ*KVDIM + gkv*64;

    // prologue: Q (hi+lo) + K0/V0 in one group
    #pragma unroll
    for (int j = 0; j < 8; j++) {
        int ci = tid + j*256;
        int arr = ci >> 10, rem = ci & 1023;
        int r = rem >> 3, c = rem & 7;
        cp_async16(&smh[(arr ? QL_B : QH_B) + r*QP + c*8],
                   (arr ? Qlb : Qhb) + (size_t)r*QDIM + c*8);
    }
    #pragma unroll
    for (int j = 0; j < 8; j++) {
        int ci = tid + j*256;
        int arr = ci >> 9, rem = ci & 511;
        int r = rem >> 3, c = rem & 7;
        size_t go = (size_t)r*KVDIM + c*8;
        const __nv_bfloat16* src = (arr == 0) ? Khb : (arr == 1) ? Klb : (arr == 2) ? Vhb : Vlb;
        int base = (arr == 0) ? KH_B(0) : (arr == 1) ? KL_B(0) : (arr == 2) ? VH_B(0) : VL_B(0);
        cp_async16(&smh[base + r*QP + c*8], src + go);
    }
    cp_commit();

    float m_i[2] = {-FLT_MAX, -FLT_MAX};
    float l_i[2] = {0.f, 0.f};
    float o[8][4];
    #pragma unroll
    for (int nf = 0; nf < 8; nf++)
        #pragma unroll
        for (int c = 0; c < 4; c++) o[nf][c] = 0.f;

    int ktmax = (128*qt + 16*warp + 15) >> 6;
    int kt_end = 2*qt + 1;
    int lrow = lane & 15, lcol = (lane >> 4) * 8;

    for (int kt = 0; kt <= kt_end; kt++) {
        int st = kt & 1;
        __syncthreads();   // all warps done with stage nx (kt-1 data)
        if (kt < kt_end) {
            int nx = st ^ 1;
            #pragma unroll
            for (int j = 0; j < 8; j++) {
                int ci = tid + j*256;
                int arr = ci >> 9, rem = ci & 511;
                int r = rem >> 3, c = rem & 7;
                size_t go = (size_t)((kt+1)*64 + r)*KVDIM + c*8;
                const __nv_bfloat16* src = (arr == 0) ? Khb : (arr == 1) ? Klb : (arr == 2) ? Vhb : Vlb;
                int base = (arr == 0) ? KH_B(nx) : (arr == 1) ? KL_B(nx) : (arr == 2) ? VH_B(nx) : VL_B(nx);
                cp_async16(&smh[base + r*QP + c*8], src + go);
            }
        }
        cp_commit();
        cp_wait<1>();
        __syncthreads();   // stage st visible to all warps

        if (kt > ktmax) continue;   // warp-level causal skip (no more block syncs below)

        // ---- S = Q K^T (3xBF16) ----
        float s[8][4];
        #pragma unroll
        for (int nf = 0; nf < 8; nf++)
            #pragma unroll
            for (int c = 0; c < 4; c++) s[nf][c] = 0.f;

        #pragma unroll
        for (int kc = 0; kc < 4; kc++) {
            int kk = kc * 16;
            uint32_t ah[4], al[4];
            {
                uint32_t ad = (uint32_t)__cvta_generic_to_shared(
                    &smh[QH_B + (m0 + lrow)*QP + kk + lcol]);
                ldmx4(ah, ad);
                ad = (uint32_t)__cvta_generic_to_shared(
                    &smh[QL_B + (m0 + lrow)*QP + kk + lcol]);
                ldmx4(al, ad);
            }
            #pragma unroll
            for (int nb = 0; nb < 4; nb++) {
                uint32_t kh[4], kl[4];
                uint32_t ad = (uint32_t)__cvta_generic_to_shared(
                    &smh[KH_B(st) + (nb*16 + lrow)*QP + kk + lcol]);
                ldmx4(kh, ad);
                ad = (uint32_t)__cvta_generic_to_shared(
                    &smh[KL_B(st) + (nb*16 + lrow)*QP + kk + lcol]);
                ldmx4(kl, ad);
                // non-trans on [n][k]: n0-7 -> (r0,r2), n8-15 -> (r1,r3)
                mma_bf16(s[nb*2],   ah, kh[0], kh[2]);
                mma_bf16(s[nb*2],   ah, kl[0], kl[2]);
                mma_bf16(s[nb*2],   al, kh[0], kh[2]);
                mma_bf16(s[nb*2+1], ah, kh[1], kh[3]);
                mma_bf16(s[nb*2+1], ah, kl[1], kl[3]);
                mma_bf16(s[nb*2+1], al, kh[1], kh[3]);
            }
        }

        // ---- causal mask ----
        if (kt*64 + 63 > 128*qt + 16*warp) {
            int r0l = 128*qt + m0 + g, r1l = r0l + 8;
            #pragma unroll
            for (int nf = 0; nf < 8; nf++) {
                int c0 = kt*64 + nf*8 + 2*tg, c1 = c0 + 1;
                if (c0 > r0l) s[nf][0] = -FLT_MAX;
                if (c1 > r0l) s[nf][1] = -FLT_MAX;
                if (c0 > r1l) s[nf][2] = -FLT_MAX;
                if (c1 > r1l) s[nf][3] = -FLT_MAX;
            }
        }

        // ---- online softmax ----
        float rm0 = -FLT_MAX, rm1 = -FLT_MAX;
        #pragma unroll
        for (int nf = 0; nf < 8; nf++) {
            rm0 = fmaxf(rm0, fmaxf(s[nf][0], s[nf][1]));
            rm1 = fmaxf(rm1, fmaxf(s[nf][2], s[nf][3]));
        }
        rm0 = fmaxf(rm0, __shfl_xor_sync(0xffffffffu, rm0, 1));
        rm0 = fmaxf(rm0, __shfl_xor_sync(0xffffffffu, rm0, 2));
        rm1 = fmaxf(rm1, __shfl_xor_sync(0xffffffffu, rm1, 1));
        rm1 = fmaxf(rm1, __shfl_xor_sync(0xffffffffu, rm1, 2));
        float mn0 = fmaxf(m_i[0], rm0), mn1 = fmaxf(m_i[1], rm1);
        float fac0 = __expf(m_i[0] - mn0), fac1 = __expf(m_i[1] - mn1);
        m_i[0] = mn0; m_i[1] = mn1;
        float rs0 = 0.f, rs1 = 0.f;
        #pragma unroll
        for (int nf = 0; nf < 8; nf++) {
            s[nf][0] = __expf(s[nf][0] - mn0); rs0 += s[nf][0];
            s[nf][1] = __expf(s[nf][1] - mn0); rs0 += s[nf][1];
            s[nf][2] = __expf(s[nf][2] - mn1); rs1 += s[nf][2];
            s[nf][3] = __expf(s[nf][3] - mn1); rs1 += s[nf][3];
        }
        rs0 += __shfl_xor_sync(0xffffffffu, rs0, 1);
        rs0 += __shfl_xor_sync(0xffffffffu, rs0, 2);
        rs1 += __shfl_xor_sync(0xffffffffu, rs1, 1);
        rs1 += __shfl_xor_sync(0xffffffffu, rs1, 2);
        l_i[0] = l_i[0]*fac0 + rs0;
        l_i[1] = l_i[1]*fac1 + rs1;
        #pragma unroll
        for (int nf = 0; nf < 8; nf++) {
            o[nf][0] *= fac0; o[nf][1] *= fac0;
            o[nf][2] *= fac1; o[nf][3] *= fac1;
        }

        // ---- P -> bf16 hi/lo smem (warp-private rows) ----
        #pragma unroll
        for (int nf = 0; nf < 8; nf++) {
            int cc = nf*8 + 2*tg;
            float l0, l1, l2, l3;
            uint32_t h01 = pack_bf16(s[nf][0], s[nf][1], &l0, &l1);
            uint32_t h23 = pack_bf16(s[nf][2], s[nf][3], &l2, &l3);
            *(uint32_t*)&smh[PH_B + (m0+g)*QP   + cc] = h01;
            *(uint32_t*)&smh[PH_B + (m0+g+8)*QP + cc] = h23;
            float d0, d1;
            *(uint32_t*)&smh[PL_B + (m0+g)*QP   + cc] = pack_bf16(l0, l1, &d0, &d1);
            *(uint32_t*)&smh[PL_B + (m0+g+8)*QP + cc] = pack_bf16(l2, l3, &d0, &d1);
        }
        __syncwarp();

        // ---- O += P V (3xBF16) ----
        #pragma unroll
        for (int kc = 0; kc < 4; kc++) {
            int kk = kc * 16;
            uint32_t ph[4], pl[4];
            {
                uint32_t ad = (uint32_t)__cvta_generic_to_shared(
                    &smh[PH_B + (m0 + lrow)*QP + kk + lcol]);
                ldmx4(ph, ad);
                ad = (uint32_t)__cvta_generic_to_shared(
                    &smh[PL_B + (m0 + lrow)*QP + kk + lcol]);
                ldmx4(pl, ad);
            }
            #pragma unroll
            for (int nb = 0; nb < 4; nb++) {
                uint32_t vh[4], vl[4];
                uint32_t ad = (uint32_t)__cvta_generic_to_shared(
                    &smh[VH_B(st) + (kk + lrow)*QP + nb*16 + lcol]);
                ldmx4t(vh, ad);
                ad = (uint32_t)__cvta_generic_to_shared(
                    &smh[VL_B(st) + (kk + lrow)*QP + nb*16 + lcol]);
                ldmx4t(vl, ad);
                // trans on [k][n]: n0-7 -> (r0,r1), n8-15 -> (r2,r3)
                mma_bf16(o[nb*2],   ph, vh[0], vh[1]);
                mma_bf16(o[nb*2],   ph, vl[0], vl[1]);
                mma_bf16(o[nb*2],   pl, vh[0], vh[1]);
                mma_bf16(o[nb*2+1], ph, vh[2], vh[3]);
                mma_bf16(o[nb*2+1], ph, vl[2], vl[3]);
                mma_bf16(o[nb*2+1], pl, vh[2], vh[3]);
            }
        }
    }

    // finalize
    float inv0 = 1.0f / l_i[0], inv1 = 1.0f / l_i[1];
    size_t row = (size_t)b*SEQ + qt*128 + m0 + g;
    float* dst0 = O + row*QDIM + h*64;
    float* dst1 = dst0 + (size_t)8*QDIM;
    #pragma unroll
    for (int nf = 0; nf < 8; nf++) {
        *(float2*)&dst0[nf*8 + 2*tg] = make_float2(o[nf][0]*inv0, o[nf][1]*inv0);
        *(float2*)&dst1[nf*8 + 2*tg] = make_float2(o[nf][2]*inv1, o[nf][3]*inv1);
    }
}

// ---------------------------------------------------------------------------
extern "C" void kernel_launch(void* const* d_in, const int* in_sizes, int n_in,
                              void* d_out, int out_size) {
    (void)in_sizes; (void)n_in; (void)out_size;
    const float* x  = (const float*)d_in[0];
    const float* wq = (const float*)d_in[1];
    const float* wk = (const float*)d_in[2];
    const float* wv = (const float*)d_in[3];
    const float* wo = (const float*)d_in[4];
    float* out = (float*)d_out;

    float *Ap, *Arp, *xr, *wqr, *wkr, *wvr, *wor;
    cudaGetSymbolAddress((void**)&Ap,  g_A);
    cudaGetSymbolAddress((void**)&Arp, g_Ar);
    cudaGetSymbolAddress((void**)&xr,  g_xr);
    cudaGetSymbolAddress((void**)&wqr, g_wqr);
    cudaGetSymbolAddress((void**)&wkr, g_wkr);
    cudaGetSymbolAddress((void**)&wvr, g_wvr);
    cudaGetSymbolAddress((void**)&wor, g_wor);

    static int attr_set = 0;
    if (!attr_set) {
        cudaFuncSetAttribute(flash4, cudaFuncAttributeMaxDynamicSharedMemorySize, FL4_SMEM);
        cudaFuncSetAttribute(qkv_kernel, cudaFuncAttributeMaxDynamicSharedMemorySize, GEMM_SMEM);
        cudaFuncSetAttribute(outproj_kernel, cudaFuncAttributeMaxDynamicSharedMemorySize, GEMM_SMEM);
        attr_set = 1;
    }

    rope_table_kernel<<<(SEQ*32 + 255)/256, 256>>>();

    round_kernel<<<(TOKENS*DMODEL/4 + 255)/256, 256>>>(x,  xr,  TOKENS*DMODEL/4);
    round_kernel<<<(DMODEL*QDIM/4  + 255)/256, 256>>>(wq, wqr, DMODEL*QDIM/4);
    round_kernel<<<(DMODEL*KVDIM/4 + 255)/256, 256>>>(wk, wkr, DMODEL*KVDIM/4);
    round_kernel<<<(DMODEL*KVDIM/4 + 255)/256, 256>>>(wv, wvr, DMODEL*KVDIM/4);
    round_kernel<<<(QDIM*DMODEL/4  + 255)/256, 256>>>(wo, wor, QDIM*DMODEL/4);

    qkv_kernel<<<dim3(24, TOKENS/128), 256, GEMM_SMEM>>>();

    flash4<<<dim3(SEQ/128, BATCH*NH), 256, FL4_SMEM>>>(Ap);

    round_kernel<<<(TOKENS*QDIM/4 + 255)/256, 256>>>(Ap, Arp, TOKENS*QDIM/4);

    outproj_kernel<<<dim3(DMODEL/128, TOKENS/128), 256, GEMM_SMEM>>>(out);
}

// round 14
// speedup vs baseline: 1.9725x; 1.2632x over previous
#include <cuda_runtime.h>
#include <cuda_bf16.h>
#include <math.h>
#include <float.h>
#include <stdint.h>

// Problem constants
#define BATCH 2
#define SEQ   2048
#define DMODEL 2048
#define NH    32
#define NKV   8
#define REP   4
#define HD    64
#define TOKENS (BATCH*SEQ)   // 4096
#define QDIM  (NH*HD)        // 2048
#define KVDIM (NKV*HD)       // 512

// Scratch (device globals: allocation-free)
__device__ __nv_bfloat16 g_Qhb[TOKENS*QDIM],  g_Qlb[TOKENS*QDIM];   // pre-scaled bf16 split Q
__device__ __nv_bfloat16 g_Khb[TOKENS*KVDIM], g_Klb[TOKENS*KVDIM];
__device__ __nv_bfloat16 g_Vhb[TOKENS*KVDIM], g_Vlb[TOKENS*KVDIM];
__device__ float g_A[TOKENS*QDIM];            // flash output (fp32)
// fragment-packed, tf32-rounded GEMM operands
__device__ float g_xp[TOKENS*DMODEL];
__device__ float g_wqp[DMODEL*QDIM];
__device__ float g_wkp[DMODEL*KVDIM];
__device__ float g_wvp[DMODEL*KVDIM];
__device__ float g_wop[QDIM*DMODEL];
__device__ float g_Apk[TOKENS*QDIM];
__device__ float g_cos[SEQ*(HD/2)];
__device__ float g_sin[SEQ*(HD/2)];

__device__ __forceinline__ uint32_t f2tf32(float x) {
    uint32_t r;
    asm("cvt.rna.tf32.f32 %0, %1;" : "=r"(r) : "f"(x));
    return r;
}
__device__ __forceinline__ float tf32f(float x) {
    return __uint_as_float(f2tf32(x));
}
__device__ __forceinline__ void mma_tf32(float* c, const uint32_t* a, uint32_t b0, uint32_t b1) {
    asm volatile("mma.sync.aligned.m16n8k8.row.col.f32.tf32.tf32.f32 "
                 "{%0,%1,%2,%3}, {%4,%5,%6,%7}, {%8,%9}, {%0,%1,%2,%3};"
                 : "+f"(c[0]), "+f"(c[1]), "+f"(c[2]), "+f"(c[3])
                 : "r"(a[0]), "r"(a[1]), "r"(a[2]), "r"(a[3]), "r"(b0), "r"(b1));
}
__device__ __forceinline__ void mma_bf16(float* c, const uint32_t* a, uint32_t b0, uint32_t b1) {
    asm volatile("mma.sync.aligned.m16n8k16.row.col.f32.bf16.bf16.f32 "
                 "{%0,%1,%2,%3}, {%4,%5,%6,%7}, {%8,%9}, {%0,%1,%2,%3};"
                 : "+f"(c[0]), "+f"(c[1]), "+f"(c[2]), "+f"(c[3])
                 : "r"(a[0]), "r"(a[1]), "r"(a[2]), "r"(a[3]), "r"(b0), "r"(b1));
}
__device__ __forceinline__ void ldmx4(uint32_t* r, uint32_t addr) {
    asm volatile("ldmatrix.sync.aligned.m8n8.x4.shared.b16 {%0,%1,%2,%3}, [%4];"
                 : "=r"(r[0]), "=r"(r[1]), "=r"(r[2]), "=r"(r[3]) : "r"(addr));
}
__device__ __forceinline__ void ldmx4t(uint32_t* r, uint32_t addr) {
    asm volatile("ldmatrix.sync.aligned.m8n8.x4.trans.shared.b16 {%0,%1,%2,%3}, [%4];"
                 : "=r"(r[0]), "=r"(r[1]), "=r"(r[2]), "=r"(r[3]) : "r"(addr));
}
__device__ __forceinline__ void cp_async16(void* smem_dst, const void* gmem_src) {
    uint32_t s = (uint32_t)__cvta_generic_to_shared(smem_dst);
    asm volatile("cp.async.cg.shared.global [%0], [%1], 16;" :: "r"(s), "l"(gmem_src));
}
__device__ __forceinline__ void cp_commit() {
    asm volatile("cp.async.commit_group;");
}
template<int N> __device__ __forceinline__ void cp_wait() {
    asm volatile("cp.async.wait_group %0;" :: "n"(N));
}
__device__ __forceinline__ uint32_t pack_bf16(float a, float b, float* ra, float* rb) {
    __nv_bfloat16 ha = __float2bfloat16(a);
    __nv_bfloat16 hb = __float2bfloat16(b);
    *ra = a - __bfloat162float(ha);
    *rb = b - __bfloat162float(hb);
    uint32_t lo = (uint32_t)__bfloat16_as_ushort(ha);
    uint32_t hi = (uint32_t)__bfloat16_as_ushort(hb);
    return lo | (hi << 16);
}

// ---------------------------------------------------------------------------
// Fragment packers (include tf32 rounding).
// A-pack: in[R,C] row-major -> out[((M*(C/8)+K)*32+l)*4 + {a0,a1,a2,a3}]
//   a0=A[M*16+g][K*8+tg], a1=+8 row, a2=+4 col, a3=both. (g=l>>2, tg=l&3)
// ---------------------------------------------------------------------------
__global__ void packA_kernel(const float* __restrict__ in, float* __restrict__ out,
                             int R, int C) {
    int idx = blockIdx.x * blockDim.x + threadIdx.x;
    int total = (R >> 4) * (C >> 3) * 32;
    if (idx >= total) return;
    int l  = idx & 31;
    int t2 = idx >> 5;
    int Kb = t2 % (C >> 3);
    int Mb = t2 / (C >> 3);
    int g = l >> 2, tg = l & 3;
    const float* src = in + (size_t)(Mb*16 + g)*C + Kb*8 + tg;
    float4 v;
    v.x = tf32f(src[0]);
    v.y = tf32f(src[(size_t)8*C]);
    v.z = tf32f(src[4]);
    v.w = tf32f(src[(size_t)8*C + 4]);
    *(float4*)(out + (size_t)idx*4) = v;
}

// B-pack: in[K,N] row-major -> out[((Nb*(K/16)+Kp)*32+l)*4 + {b0k0,b1k0,b0k1,b1k1}]
//   b0 = B[Kp*16+tg][Nb*8+g], b1 = +4 rows; k1 half at +8 rows.
__global__ void packB_kernel(const float* __restrict__ in, float* __restrict__ out,
                             int K, int N) {
    int idx = blockIdx.x * blockDim.x + threadIdx.x;
    int total = (N >> 3) * (K >> 4) * 32;
    if (idx >= total) return;
    int l  = idx & 31;
    int t2 = idx >> 5;
    int Kp = t2 % (K >> 4);
    int Nb = t2 / (K >> 4);
    int g = l >> 2, tg = l & 3;
    const float* src = in + (size_t)(Kp*16 + tg)*N + Nb*8 + g;
    float4 v;
    v.x = tf32f(src[0]);
    v.y = tf32f(src[(size_t)4*N]);
    v.z = tf32f(src[(size_t)8*N]);
    v.w = tf32f(src[(size_t)12*N]);
    *(float4*)(out + (size_t)idx*4) = v;
}

// ---------------------------------------------------------------------------
// RoPE tables
// ---------------------------------------------------------------------------
__global__ void rope_table_kernel() {
    int idx = blockIdx.x * blockDim.x + threadIdx.x;
    if (idx >= SEQ*(HD/2)) return;
    int pos = idx >> 5;
    int i   = idx & 31;
    double expo = (2.0 * i) / 64.0;
    float invf = (float)(1.0 / pow(10000.0, expo));
    float fr = (float)pos * invf;
    double a = (double)fr;
    g_cos[idx] = (float)cos(a);
    g_sin[idx] = (float)sin(a);
}

// ---------------------------------------------------------------------------
// Pipelined tf32 GEMM on fragment-packed operands.
//   mode bit0: RoPE   bit1: scale 0.125   bit2: split into bf16 hi/lo (Chb,Clb)
// smem/stage: A 2048 floats ([mb8][k8x2][lane][4]), B 2048 ([nb16][lane][4]).
// ---------------------------------------------------------------------------
#define GK 2048
#define NSTG 3
#define ASTG2 2048
#define BSTG2 2048
#define GEMM_SMEM (NSTG*(ASTG2+BSTG2)*4)   // 49152 B

__device__ __forceinline__ void gemm_body(const float* __restrict__ Apk,
                                          const float* __restrict__ Bpk,
                                          float* __restrict__ Cf,
                                          __nv_bfloat16* __restrict__ Chb,
                                          __nv_bfloat16* __restrict__ Clb,
                                          int N, int by, int cb, int mode) {
    extern __shared__ float sm[];
    float* As = sm;
    float* Bs = sm + NSTG*ASTG2;

    int tid  = threadIdx.x;
    int lane = tid & 31, warp = tid >> 5;
    int wm = warp & 3, wn = warp >> 2;
    int m_warp = wm * 32, n_warp = wn * 64;
    int g  = lane >> 2;
    int tg = lane & 3;

    // cp.async assignments
    int a_mb = tid >> 5, a_l = tid & 31;     // A: 8 m-blocks x 32 lanes
    int b_nb = tid >> 4, b_sub = tid & 15;   // B: 16 n-blocks x 16 subs (8 floats each)

    const float* Abase = Apk + (((size_t)(by*8 + a_mb))*(GK/8))*128 + a_l*4;
    const float* Bbase = Bpk + (((size_t)(cb*16 + b_nb))*(GK/16))*128 + b_sub*8;

    float acc[2][8][4];
    #pragma unroll
    for (int mi = 0; mi < 2; mi++)
        #pragma unroll
        for (int ni = 0; ni < 8; ni++)
            #pragma unroll
            for (int c = 0; c < 4; c++) acc[mi][ni][c] = 0.f;

    #pragma unroll
    for (int s = 0; s < NSTG-1; s++) {
        float* as = As + s*ASTG2;
        float* bs = Bs + s*BSTG2;
        cp_async16(&as[a_mb*256 + a_l*4],       Abase + (size_t)(2*s)*128);
        cp_async16(&as[a_mb*256 + 128 + a_l*4], Abase + (size_t)(2*s+1)*128);
        cp_async16(&bs[b_nb*128 + b_sub*8],     Bbase + (size_t)s*128);
        cp_async16(&bs[b_nb*128 + b_sub*8 + 4], Bbase + (size_t)s*128 + 4);
        cp_commit();
    }

    const int NITER = GK / 16;
    int s = 0;
    for (int it = 0; it < NITER; it++) {
        cp_wait<NSTG-2>();
        __syncthreads();

        int itpre = it + NSTG - 1;
        if (itpre < NITER) {
            int sp = itpre % NSTG;
            float* as = As + sp*ASTG2;
            float* bs = Bs + sp*BSTG2;
            cp_async16(&as[a_mb*256 + a_l*4],       Abase + (size_t)(2*itpre)*128);
            cp_async16(&as[a_mb*256 + 128 + a_l*4], Abase + (size_t)(2*itpre+1)*128);
            cp_async16(&bs[b_nb*128 + b_sub*8],     Bbase + (size_t)itpre*128);
            cp_async16(&bs[b_nb*128 + b_sub*8 + 4], Bbase + (size_t)itpre*128 + 4);
        }
        cp_commit();

        const float* as = As + s*ASTG2;
        const float* bs = Bs + s*BSTG2;

        float4 bv[8];
        #pragma unroll
        for (int ni = 0; ni < 8; ni++)
            bv[ni] = *(const float4*)(bs + (n_warp/8 + ni)*128 + lane*4);

        #pragma unroll
        for (int kk8 = 0; kk8 < 2; kk8++) {
            uint32_t afr[2][4];
            #pragma unroll
            for (int mi = 0; mi < 2; mi++) {
                float4 av = *(const float4*)(as + (wm*2 + mi)*256 + kk8*128 + lane*4);
                afr[mi][0] = __float_as_uint(av.x);
                afr[mi][1] = __float_as_uint(av.y);
                afr[mi][2] = __float_as_uint(av.z);
                afr[mi][3] = __float_as_uint(av.w);
            }
            #pragma unroll
            for (int mi = 0; mi < 2; mi++)
                #pragma unroll
                for (int ni = 0; ni < 8; ni++) {
                    uint32_t b0 = __float_as_uint(kk8 ? bv[ni].z : bv[ni].x);
                    uint32_t b1 = __float_as_uint(kk8 ? bv[ni].w : bv[ni].y);
                    mma_tf32(acc[mi][ni], afr[mi], b0, b1);
                }
        }
        s = (s + 1) % NSTG;
    }

    // ---- fused RoPE (warp tile spans exactly one head) ----
    if (mode & 1) {
        #pragma unroll
        for (int mi = 0; mi < 2; mi++) {
            int ra = by*128 + m_warp + mi*16 + g;
            int pa = ra & (SEQ-1);
            int pb = (ra + 8) & (SEQ-1);
            #pragma unroll
            for (int ni = 0; ni < 4; ni++) {
                int i0 = ni*8 + tg*2;
                float ca0 = g_cos[pa*32 + i0],   sa0 = g_sin[pa*32 + i0];
                float ca1 = g_cos[pa*32 + i0+1], sa1 = g_sin[pa*32 + i0+1];
                float cb0 = g_cos[pb*32 + i0],   sb0 = g_sin[pb*32 + i0];
                float cb1 = g_cos[pb*32 + i0+1], sb1 = g_sin[pb*32 + i0+1];
                float x1, x2;
                x1 = acc[mi][ni][0]; x2 = acc[mi][ni+4][0];
                acc[mi][ni][0] = x1*ca0 - x2*sa0; acc[mi][ni+4][0] = x1*sa0 + x2*ca0;
                x1 = acc[mi][ni][1]; x2 = acc[mi][ni+4][1];
                acc[mi][ni][1] = x1*ca1 - x2*sa1; acc[mi][ni+4][1] = x1*sa1 + x2*ca1;
                x1 = acc[mi][ni][2]; x2 = acc[mi][ni+4][2];
                acc[mi][ni][2] = x1*cb0 - x2*sb0; acc[mi][ni+4][2] = x1*sb0 + x2*cb0;
                x1 = acc[mi][ni][3]; x2 = acc[mi][ni+4][3];
                acc[mi][ni][3] = x1*cb1 - x2*sb1; acc[mi][ni+4][3] = x1*sb1 + x2*cb1;
            }
        }
    }

    float mul = (mode & 2) ? 0.125f : 1.0f;
    size_t rowbase = (size_t)by * 128 + m_warp + g;
    int colbase = cb * 128 + n_warp + tg*2;
    if (mode & 4) {
        #pragma unroll
        for (int mi = 0; mi < 2; mi++) {
            size_t r0 = rowbase + mi*16;
            #pragma unroll
            for (int ni = 0; ni < 8; ni++) {
                int c = colbase + ni*8;
                float l0, l1, l2, l3;
                uint32_t h01 = pack_bf16(acc[mi][ni][0]*mul, acc[mi][ni][1]*mul, &l0, &l1);
                uint32_t h23 = pack_bf16(acc[mi][ni][2]*mul, acc[mi][ni][3]*mul, &l2, &l3);
                *(uint32_t*)&Chb[r0*N + c]     = h01;
                *(uint32_t*)&Chb[(r0+8)*N + c] = h23;
                float d0, d1;
                *(uint32_t*)&Clb[r0*N + c]     = pack_bf16(l0, l1, &d0, &d1);
                *(uint32_t*)&Clb[(r0+8)*N + c] = pack_bf16(l2, l3, &d0, &d1);
            }
        }
    } else {
        #pragma unroll
        for (int mi = 0; mi < 2; mi++) {
            size_t r0 = rowbase + mi*16;
            #pragma unroll
            for (int ni = 0; ni < 8; ni++) {
                int c = colbase + ni*8;
                *(float2*)&Cf[r0*N + c]     = make_float2(acc[mi][ni][0], acc[mi][ni][1]);
                *(float2*)&Cf[(r0+8)*N + c] = make_float2(acc[mi][ni][2], acc[mi][ni][3]);
            }
        }
    }
}

// Fused QKV projection + RoPE + bf16-split. grid=(24,32)
__global__ __launch_bounds__(256) void qkv_kernel() {
    int bx = blockIdx.x;
    const float* B; __nv_bfloat16 *Ch, *Cl; int N, cb, mode;
    if (bx < 16)      { B = g_wqp; Ch = g_Qhb; Cl = g_Qlb; N = QDIM;  cb = bx;      mode = 7; }
    else if (bx < 20) { B = g_wkp; Ch = g_Khb; Cl = g_Klb; N = KVDIM; cb = bx - 16; mode = 5; }
    else              { B = g_wvp; Ch = g_Vhb; Cl = g_Vlb; N = KVDIM; cb = bx - 20; mode = 4; }
    gemm_body(g_xp, B, nullptr, Ch, Cl, N, blockIdx.y, cb, mode);
}

// Output projection. grid=(16,32)
__global__ __launch_bounds__(256) void outproj_kernel(float* __restrict__ out) {
    gemm_body(g_Apk, g_wop, out, nullptr, nullptr, DMODEL, blockIdx.y, blockIdx.x, 0);
}

// ---------------------------------------------------------------------------
// Flash attention v4 (unchanged from R13): 3xBF16 + ldmatrix, q-tile 128,
// 8 warps, double-buffered K/V, dedicated P smem.
// ---------------------------------------------------------------------------
#define QP 72
#define QH_B 0
#define QL_B (128*QP)
#define ST_B (2*128*QP)
#define SS   (4*64*QP)
#define KH_B(s) (ST_B + (s)*SS)
#define KL_B(s) (KH_B(s) + 64*QP)
#define VH_B(s) (KH_B(s) + 2*64*QP)
#define VL_B(s) (KH_B(s) + 3*64*QP)
#define PH_B (ST_B + 2*SS)
#define PL_B (PH_B + 128*QP)
#define FL4_SMEM ((PL_B + 128*QP)*2)   // 147456 B

__global__ __launch_bounds__(256) void flash4(float* __restrict__ O) {
    extern __shared__ __nv_bfloat16 smh[];

    int qt = blockIdx.x;
    int bh = blockIdx.y;
    int b = bh >> 5, h = bh & 31, gkv = h >> 2;
    int tid = threadIdx.x;
    int lane = tid & 31, warp = tid >> 5;
    int g = lane >> 2, tg = lane & 3;
    int m0 = warp * 16;

    const __nv_bfloat16* Qhb = g_Qhb + ((size_t)b*SEQ + qt*128)*QDIM + h*64;
    const __nv_bfloat16* Qlb = g_Qlb + ((size_t)b*SEQ + qt*128)*QDIM + h*64;
    const __nv_bfloat16* Khb = g_Khb + (size_t)b*SEQ*KVDIM + gkv*64;
    const __nv_bfloat16* Klb = g_Klb + (size_t)b*SEQ*KVDIM + gkv*64;
    const __nv_bfloat16* Vhb = g_Vhb + (size_t)b*SEQ*KVDIM + gkv*64;
    const __nv_bfloat16* Vlb = g_Vlb + (size_t)b*SEQ*KVDIM + gkv*64;

    #pragma unroll
    for (int j = 0; j < 8; j++) {
        int ci = tid + j*256;
        int arr = ci >> 10, rem = ci & 1023;
        int r = rem >> 3, c = rem & 7;
        cp_async16(&smh[(arr ? QL_B : QH_B) + r*QP + c*8],
                   (arr ? Qlb : Qhb) + (size_t)r*QDIM + c*8);
    }
    #pragma unroll
    for (int j = 0; j < 8; j++) {
        int ci = tid + j*256;
        int arr = ci >> 9, rem = ci & 511;
        int r = rem >> 3, c = rem & 7;
        size_t go = (size_t)r*KVDIM + c*8;
        const __nv_bfloat16* src = (arr == 0) ? Khb : (arr == 1) ? Klb : (arr == 2) ? Vhb : Vlb;
        int base = (arr == 0) ? KH_B(0) : (arr == 1) ? KL_B(0) : (arr == 2) ? VH_B(0) : VL_B(0);
        cp_async16(&smh[base + r*QP + c*8], src + go);
    }
    cp_commit();

    float m_i[2] = {-FLT_MAX, -FLT_MAX};
    float l_i[2] = {0.f, 0.f};
    float o[8][4];
    #pragma unroll
    for (int nf = 0; nf < 8; nf++)
        #pragma unroll
        for (int c = 0; c < 4; c++) o[nf][c] = 0.f;

    int ktmax = (128*qt + 16*warp + 15) >> 6;
    int kt_end = 2*qt + 1;
    int lrow = lane & 15, lcol = (lane >> 4) * 8;

    for (int kt = 0; kt <= kt_end; kt++) {
        int st = kt & 1;
        __syncthreads();
        if (kt < kt_end) {
            int nx = st ^ 1;
            #pragma unroll
            for (int j = 0; j < 8; j++) {
                int ci = tid + j*256;
                int arr = ci >> 9, rem = ci & 511;
                int r = rem >> 3, c = rem & 7;
                size_t go = (size_t)((kt+1)*64 + r)*KVDIM + c*8;
                const __nv_bfloat16* src = (arr == 0) ? Khb : (arr == 1) ? Klb : (arr == 2) ? Vhb : Vlb;
                int base = (arr == 0) ? KH_B(nx) : (arr == 1) ? KL_B(nx) : (arr == 2) ? VH_B(nx) : VL_B(nx);
                cp_async16(&smh[base + r*QP + c*8], src + go);
            }
        }
        cp_commit();
        cp_wait<1>();
        __syncthreads();

        if (kt > ktmax) continue;

        float s[8][4];
        #pragma unroll
        for (int nf = 0; nf < 8; nf++)
            #pragma unroll
            for (int c = 0; c < 4; c++) s[nf][c] = 0.f;

        #pragma unroll
        for (int kc = 0; kc < 4; kc++) {
            int kk = kc * 16;
            uint32_t ah[4], al[4];
            {
                uint32_t ad = (uint32_t)__cvta_generic_to_shared(
                    &smh[QH_B + (m0 + lrow)*QP + kk + lcol]);
                ldmx4(ah, ad);
                ad = (uint32_t)__cvta_generic_to_shared(
                    &smh[QL_B + (m0 + lrow)*QP + kk + lcol]);
                ldmx4(al, ad);
            }
            #pragma unroll
            for (int nb = 0; nb < 4; nb++) {
                uint32_t kh[4], kl[4];
                uint32_t ad = (uint32_t)__cvta_generic_to_shared(
                    &smh[KH_B(st) + (nb*16 + lrow)*QP + kk + lcol]);
                ldmx4(kh, ad);
                ad = (uint32_t)__cvta_generic_to_shared(
                    &smh[KL_B(st) + (nb*16 + lrow)*QP + kk + lcol]);
                ldmx4(kl, ad);
                mma_bf16(s[nb*2],   ah, kh[0], kh[2]);
                mma_bf16(s[nb*2],   ah, kl[0], kl[2]);
                mma_bf16(s[nb*2],   al, kh[0], kh[2]);
                mma_bf16(s[nb*2+1], ah, kh[1], kh[3]);
                mma_bf16(s[nb*2+1], ah, kl[1], kl[3]);
                mma_bf16(s[nb*2+1], al, kh[1], kh[3]);
            }
        }

        if (kt*64 + 63 > 128*qt + 16*warp) {
            int r0l = 128*qt + m0 + g, r1l = r0l + 8;
            #pragma unroll
            for (int nf = 0; nf < 8; nf++) {
                int c0 = kt*64 + nf*8 + 2*tg, c1 = c0 + 1;
                if (c0 > r0l) s[nf][0] = -FLT_MAX;
                if (c1 > r0l) s[nf][1] = -FLT_MAX;
                if (c0 > r1l) s[nf][2] = -FLT_MAX;
                if (c1 > r1l) s[nf][3] = -FLT_MAX;
            }
        }

        float rm0 = -FLT_MAX, rm1 = -FLT_MAX;
        #pragma unroll
        for (int nf = 0; nf < 8; nf++) {
            rm0 = fmaxf(rm0, fmaxf(s[nf][0], s[nf][1]));
            rm1 = fmaxf(rm1, fmaxf(s[nf][2], s[nf][3]));
        }
        rm0 = fmaxf(rm0, __shfl_xor_sync(0xffffffffu, rm0, 1));
        rm0 = fmaxf(rm0, __shfl_xor_sync(0xffffffffu, rm0, 2));
        rm1 = fmaxf(rm1, __shfl_xor_sync(0xffffffffu, rm1, 1));
        rm1 = fmaxf(rm1, __shfl_xor_sync(0xffffffffu, rm1, 2));
        float mn0 = fmaxf(m_i[0], rm0), mn1 = fmaxf(m_i[1], rm1);
        float fac0 = __expf(m_i[0] - mn0), fac1 = __expf(m_i[1] - mn1);
        m_i[0] = mn0; m_i[1] = mn1;
        float rs0 = 0.f, rs1 = 0.f;
        #pragma unroll
        for (int nf = 0; nf < 8; nf++) {
            s[nf][0] = __expf(s[nf][0] - mn0); rs0 += s[nf][0];
            s[nf][1] = __expf(s[nf][1] - mn0); rs0 += s[nf][1];
            s[nf][2] = __expf(s[nf][2] - mn1); rs1 += s[nf][2];
            s[nf][3] = __expf(s[nf][3] - mn1); rs1 += s[nf][3];
        }
        rs0 += __shfl_xor_sync(0xffffffffu, rs0, 1);
        rs0 += __shfl_xor_sync(0xffffffffu, rs0, 2);
        rs1 += __shfl_xor_sync(0xffffffffu, rs1, 1);
        rs1 += __shfl_xor_sync(0xffffffffu, rs1, 2);
        l_i[0] = l_i[0]*fac0 + rs0;
        l_i[1] = l_i[1]*fac1 + rs1;
        #pragma unroll
        for (int nf = 0; nf < 8; nf++) {
            o[nf][0] *= fac0; o[nf][1] *= fac0;
            o[nf][2] *= fac1; o[nf][3] *= fac1;
        }

        #pragma unroll
        for (int nf = 0; nf < 8; nf++) {
            int cc = nf*8 + 2*tg;
            float l0, l1, l2, l3;
            uint32_t h01 = pack_bf16(s[nf][0], s[nf][1], &l0, &l1);
            uint32_t h23 = pack_bf16(s[nf][2], s[nf][3], &l2, &l3);
            *(uint32_t*)&smh[PH_B + (m0+g)*QP   + cc] = h01;
            *(uint32_t*)&smh[PH_B + (m0+g+8)*QP + cc] = h23;
            float d0, d1;
            *(uint32_t*)&smh[PL_B + (m0+g)*QP   + cc] = pack_bf16(l0, l1, &d0, &d1);
            *(uint32_t*)&smh[PL_B + (m0+g+8)*QP + cc] = pack_bf16(l2, l3, &d0, &d1);
        }
        __syncwarp();

        #pragma unroll
        for (int kc = 0; kc < 4; kc++) {
            int kk = kc * 16;
            uint32_t ph[4], pl[4];
            {
                uint32_t ad = (uint32_t)__cvta_generic_to_shared(
                    &smh[PH_B + (m0 + lrow)*QP + kk + lcol]);
                ldmx4(ph, ad);
                ad = (uint32_t)__cvta_generic_to_shared(
                    &smh[PL_B + (m0 + lrow)*QP + kk + lcol]);
                ldmx4(pl, ad);
            }
            #pragma unroll
            for (int nb = 0; nb < 4; nb++) {
                uint32_t vh[4], vl[4];
                uint32_t ad = (uint32_t)__cvta_generic_to_shared(
                    &smh[VH_B(st) + (kk + lrow)*QP + nb*16 + lcol]);
                ldmx4t(vh, ad);
                ad = (uint32_t)__cvta_generic_to_shared(
                    &smh[VL_B(st) + (kk + lrow)*QP + nb*16 + lcol]);
                ldmx4t(vl, ad);
                mma_bf16(o[nb*2],   ph, vh[0], vh[1]);
                mma_bf16(o[nb*2],   ph, vl[0], vl[1]);
                mma_bf16(o[nb*2],   pl, vh[0], vh[1]);
                mma_bf16(o[nb*2+1], ph, vh[2], vh[3]);
                mma_bf16(o[nb*2+1], ph, vl[2], vl[3]);
                mma_bf16(o[nb*2+1], pl, vh[2], vh[3]);
            }
        }
    }

    float inv0 = 1.0f / l_i[0], inv1 = 1.0f / l_i[1];
    size_t row = (size_t)b*SEQ + qt*128 + m0 + g;
    float* dst0 = O + row*QDIM + h*64;
    float* dst1 = dst0 + (size_t)8*QDIM;
    #pragma unroll
    for (int nf = 0; nf < 8; nf++) {
        *(float2*)&dst0[nf*8 + 2*tg] = make_float2(o[nf][0]*inv0, o[nf][1]*inv0);
        *(float2*)&dst1[nf*8 + 2*tg] = make_float2(o[nf][2]*inv1, o[nf][3]*inv1);
    }
}

// ---------------------------------------------------------------------------
extern "C" void kernel_launch(void* const* d_in, const int* in_sizes, int n_in,
                              void* d_out, int out_size) {
    (void)in_sizes; (void)n_in; (void)out_size;
    const float* x  = (const float*)d_in[0];
    const float* wq = (const float*)d_in[1];
    const float* wk = (const float*)d_in[2];
    const float* wv = (const float*)d_in[3];
    const float* wo = (const float*)d_in[4];
    float* out = (float*)d_out;

    float *Ap, *Apkp, *xp, *wqp, *wkp, *wvp, *wop;
    cudaGetSymbolAddress((void**)&Ap,   g_A);
    cudaGetSymbolAddress((void**)&Apkp, g_Apk);
    cudaGetSymbolAddress((void**)&xp,   g_xp);
    cudaGetSymbolAddress((void**)&wqp,  g_wqp);
    cudaGetSymbolAddress((void**)&wkp,  g_wkp);
    cudaGetSymbolAddress((void**)&wvp,  g_wvp);
    cudaGetSymbolAddress((void**)&wop,  g_wop);

    static int attr_set = 0;
    if (!attr_set) {
        cudaFuncSetAttribute(flash4, cudaFuncAttributeMaxDynamicSharedMemorySize, FL4_SMEM);
        cudaFuncSetAttribute(qkv_kernel, cudaFuncAttributeMaxDynamicSharedMemorySize, GEMM_SMEM);
        cudaFuncSetAttribute(outproj_kernel, cudaFuncAttributeMaxDynamicSharedMemorySize, GEMM_SMEM);
        attr_set = 1;
    }

    rope_table_kernel<<<(SEQ*32 + 255)/256, 256>>>();

    // fragment packing (+tf32 round)
    packA_kernel<<<(TOKENS/16)*(DMODEL/8)*32/256, 256>>>(x,  xp,  TOKENS, DMODEL);
    packB_kernel<<<(QDIM/8)*(DMODEL/16)*32/256,  256>>>(wq, wqp, DMODEL, QDIM);
    packB_kernel<<<(KVDIM/8)*(DMODEL/16)*32/256, 256>>>(wk, wkp, DMODEL, KVDIM);
    packB_kernel<<<(KVDIM/8)*(DMODEL/16)*32/256, 256>>>(wv, wvp, DMODEL, KVDIM);
    packB_kernel<<<(DMODEL/8)*(QDIM/16)*32/256,  256>>>(wo, wop, QDIM, DMODEL);

    qkv_kernel<<<dim3(24, TOKENS/128), 256, GEMM_SMEM>>>();

    flash4<<<dim3(SEQ/128, BATCH*NH), 256, FL4_SMEM>>>(Ap);

    packA_kernel<<<(TOKENS/16)*(QDIM/8)*32/256, 256>>>(Ap, Apkp, TOKENS, QDIM);

    outproj_kernel<<<dim3(DMODEL/128, TOKENS/128), 256, GEMM_SMEM>>>(out);
}